// round 13
// baseline (speedup 1.0000x reference)
#include <cuda_runtime.h>
#include <cuda_bf16.h>
#include <cuda_fp16.h>
#include <math.h>
#include <stdint.h>

#define BATCH   8192
#define IN_DIM  512
#define EMB     64
#define KC      256
#define DENSE   1152
#define NTRI    2080
#define NFEAT   2176
#define K3Q     (3*NFEAT)
#define LP_OFF  (BATCH*IN_DIM)
#define IDX_OFF (LP_OFF + BATCH*KC)
#define LOG2PI_F 1.8378770664093453f

// ---------------- scratch ----------------
__device__ __align__(128) __nv_bfloat16 g_xs  [BATCH * 2 * IN_DIM];
__device__ __align__(128) __nv_bfloat16 g_h1s [BATCH * 3 * DENSE];   // enc: 2-plane bf16 / dec: 2-plane fp16
__device__ __align__(128) __nv_bfloat16 g_h2s [BATCH * 3 * DENSE];   // enc: 3-plane bf16 (for e3) / dec: 2-plane fp16
__device__ __align__(128) __half        g_qs  [BATCH * 2 * EMB];
__device__ __align__(128) __nv_bfloat16 g_eW1s[DENSE * 2 * IN_DIM];
__device__ __align__(128) __nv_bfloat16 g_eW2s[DENSE * 2 * DENSE];
__device__ __align__(128) __nv_bfloat16 g_eW3s[EMB   * 3 * DENSE];   // old-style 3-plane for e3
__device__ __align__(128) __half        g_dW1s[DENSE * EMB];
__device__ __align__(128) __half        g_dW2s[DENSE * DENSE];
__device__ __align__(128) __half        g_dW3s[IN_DIM * DENSE];
__device__ __align__(128) __nv_bfloat16 g_Gs  [(size_t)BATCH * K3Q]; // lp fallback
__device__ __align__(128) __nv_bfloat16 g_Wp  [(size_t)KC * K3Q];
__device__ float g_enc [BATCH * EMB];
__device__ float g_Linv[KC * EMB * EMB];
__device__ float g_Lraw[KC * EMB * EMB];
__device__ float g_logdet[KC];
__device__ int   g_idx [BATCH];
__device__ int2  g_top2[BATCH];
__device__ int   g_ident;

// ---------------- helpers ----------------
__device__ __forceinline__ float selu_f(float x) {
    const float scale = 1.0507009873554805f;
    const float alpha = 1.6732632423543772f;
    return scale * (x > 0.f ? x : alpha * expm1f(x));
}
__device__ __forceinline__ void split2(float v, __nv_bfloat16& hi, __nv_bfloat16& lo) {
    hi = __float2bfloat16(v);
    lo = __float2bfloat16(v - __bfloat162float(hi));
}
__device__ __forceinline__ void split2h(float v, __half& hi, __half& lo) {
    hi = __float2half_rn(v);
    lo = __float2half_rn(v - __half2float(hi));
}
__device__ __forceinline__ uint32_t pack_bf2(__nv_bfloat16 a, __nv_bfloat16 b) {
    __nv_bfloat162 t; t.x = a; t.y = b;
    return *reinterpret_cast<uint32_t*>(&t);
}
__device__ __forceinline__ uint32_t pack_h2(__half a, __half b) {
    __half2 t; t.x = a; t.y = b;
    return *reinterpret_cast<uint32_t*>(&t);
}
__device__ __forceinline__ uint32_t smem_u32(const void* p) {
    uint32_t a;
    asm("{ .reg .u64 t; cvta.to.shared.u64 t, %1; cvt.u32.u64 %0, t; }" : "=r"(a) : "l"(p));
    return a;
}
__device__ __forceinline__ void cp16(uint32_t dst, const void* src) {
    asm volatile("cp.async.cg.shared.global [%0], [%1], 16;" :: "r"(dst), "l"(src));
}
__device__ __forceinline__ uint32_t sw128(uint32_t off) { return off ^ ((off >> 3) & 0x70); }

__device__ __forceinline__ void ldsm4(uint32_t& r0, uint32_t& r1, uint32_t& r2, uint32_t& r3,
                                      uint32_t addr) {
    asm volatile("ldmatrix.sync.aligned.m8n8.x4.shared.b16 {%0,%1,%2,%3}, [%4];"
        : "=r"(r0), "=r"(r1), "=r"(r2), "=r"(r3) : "r"(addr));
}
__device__ __forceinline__ void mma_bf16(float* c,
    uint32_t a0, uint32_t a1, uint32_t a2, uint32_t a3, uint32_t b0, uint32_t b1) {
    asm volatile("mma.sync.aligned.m16n8k16.row.col.f32.bf16.bf16.f32 "
        "{%0,%1,%2,%3}, {%4,%5,%6,%7}, {%8,%9}, {%0,%1,%2,%3};"
        : "+f"(c[0]), "+f"(c[1]), "+f"(c[2]), "+f"(c[3])
        : "r"(a0), "r"(a1), "r"(a2), "r"(a3), "r"(b0), "r"(b1));
}
__device__ __forceinline__ void mma_f16(float* c,
    uint32_t a0, uint32_t a1, uint32_t a2, uint32_t a3, uint32_t b0, uint32_t b1) {
    asm volatile("mma.sync.aligned.m16n8k16.row.col.f32.f16.f16.f32 "
        "{%0,%1,%2,%3}, {%4,%5,%6,%7}, {%8,%9}, {%0,%1,%2,%3};"
        : "+f"(c[0]), "+f"(c[1]), "+f"(c[2]), "+f"(c[3])
        : "r"(a0), "r"(a1), "r"(a2), "r"(a3), "r"(b0), "r"(b1));
}
__device__ __forceinline__ void tri_ij(int t, int& i, int& j) {
    int ii = (int)((sqrtf(8.f * (float)t + 1.f) - 1.f) * 0.5f);
    if ((ii + 1) * (ii + 2) / 2 <= t) ii++;
    if (ii * (ii + 1) / 2 > t) ii--;
    i = ii; j = t - ii * (ii + 1) / 2;
}

// ---------------- split conversions ----------------
// 2-plane bf16 [hi | lo] (used for both A-side and W-side of fused-3 GEMMs)
__global__ void split2_kernel(const float* __restrict__ in, __nv_bfloat16* __restrict__ out,
                              int total, int K) {
    int i4 = (blockIdx.x * blockDim.x + threadIdx.x) * 4;
    if (i4 >= total) return;
    int r = i4 / K, c = i4 % K;
    float4 v = *(const float4*)(in + i4);
    __nv_bfloat16 h0, l0, h1, l1, h2, l2, h3, l3;
    split2(v.x, h0, l0); split2(v.y, h1, l1); split2(v.z, h2, l2); split2(v.w, h3, l3);
    uint32_t hA = pack_bf2(h0, h1), hB = pack_bf2(h2, h3);
    uint32_t lA = pack_bf2(l0, l1), lB = pack_bf2(l2, l3);
    size_t b = (size_t)r * 2 * K + c;
    *(uint32_t*)(out + b)     = hA; *(uint32_t*)(out + b + 2)     = hB;
    *(uint32_t*)(out + b + K) = lA; *(uint32_t*)(out + b + K + 2) = lB;
}
// old 3-plane W-side [hi | lo | hi] (for e3 + lp fallback)
__global__ void split_w_kernel(const float* __restrict__ in, __nv_bfloat16* __restrict__ out,
                               int total, int K) {
    int i4 = (blockIdx.x * blockDim.x + threadIdx.x) * 4;
    if (i4 >= total) return;
    int r = i4 / K, c = i4 % K;
    float4 v = *(const float4*)(in + i4);
    __nv_bfloat16 h0, l0, h1, l1, h2, l2, h3, l3;
    split2(v.x, h0, l0); split2(v.y, h1, l1); split2(v.z, h2, l2); split2(v.w, h3, l3);
    uint32_t hA = pack_bf2(h0, h1), hB = pack_bf2(h2, h3);
    uint32_t lA = pack_bf2(l0, l1), lB = pack_bf2(l2, l3);
    size_t b = (size_t)r * 3 * K + c;
    *(uint32_t*)(out + b)         = hA; *(uint32_t*)(out + b + 2)         = hB;
    *(uint32_t*)(out + b + K)     = lA; *(uint32_t*)(out + b + K + 2)     = lB;
    *(uint32_t*)(out + b + 2 * K) = hA; *(uint32_t*)(out + b + 2 * K + 2) = hB;
}
// plain fp16 convert (decoder W, 1 plane)
__global__ void cvt_h_kernel(const float* __restrict__ in, __half* __restrict__ out, int total) {
    int i4 = (blockIdx.x * blockDim.x + threadIdx.x) * 4;
    if (i4 >= total) return;
    float4 v = *(const float4*)(in + i4);
    uint32_t a = pack_h2(__float2half_rn(v.x), __float2half_rn(v.y));
    uint32_t b = pack_h2(__float2half_rn(v.z), __float2half_rn(v.w));
    *(uint32_t*)(out + i4)     = a;
    *(uint32_t*)(out + i4 + 2) = b;
}

// ================= fused-plane GEMM (crossbar-optimized) =================
// BM=256, BN=128, 512 threads (16 warps, 4m x 4n), warp tile 64x32. 2-stage.
// TERMS=3 (bf16): A=[hi|lo] stride 2K, W=[hi|lo] stride 2K;
//   acc += A_hi*W_hi + A_hi*W_lo + A_lo*W_hi  (fragment reuse within each k-step)
// TERMS=2 (fp16): A=[hi|lo] stride 2K, W 1 plane stride K; acc += (A_hi+A_lo)*W
// MODE 0: fp32 +bias. MODE 1: SELU + (bf16 3-plane | fp16 2-plane). MODE 3: SELU + bf16 2-plane.
template<int TERMS, int MODE, int FP16>
__global__ void __launch_bounds__(512) gemm_fused(
    const void* __restrict__ Ain, const void* __restrict__ Win,
    const float* __restrict__ bias, void* __restrict__ Cout,
    int N, int K)
{
    constexpr int BM = 256, BN = 128;
    constexpr int AT = BM * 128;               // one A tile (256 x 64 bf16/fp16 = 32KB)
    constexpr int WT = BN * 128;               // one W tile (16KB)
    constexpr int STAGE = 2 * AT + (TERMS == 3 ? 2 : 1) * WT;
    constexpr int MI = 4, NF = 4;              // warp tile 64 x 32

    const uint16_t* A = (const uint16_t*)Ain;
    const uint16_t* W = (const uint16_t*)Win;
    const int wstride = (TERMS == 3) ? 2 * K : K;

    extern __shared__ __align__(1024) char smem[];
    const uint32_t sbase = smem_u32(smem);

    const int tid = threadIdx.x;
    const int lane = tid & 31;
    const int wid = tid >> 5;                  // 0..15
    const int wm = wid & 3;                    // rows wm*64
    const int wn = wid >> 2;                   // cols wn*32
    const int bm = blockIdx.y * BM;
    const int bn = blockIdx.x * BN;

    float acc[MI][NF][4];
#pragma unroll
    for (int i = 0; i < MI; i++)
#pragma unroll
        for (int j = 0; j < NF; j++)
#pragma unroll
            for (int c = 0; c < 4; c++) acc[i][j][c] = 0.f;

    const int nc = K >> 6;

    auto load_stage = [&](int c, int s) {
        const uint32_t base = sbase + (uint32_t)s * STAGE;
        // A_hi: 256 rows x 8 x 16B = 2048 cp16 -> 4/thread
#pragma unroll
        for (int t = 0; t < 4; t++) {
            int idx = tid + t * 512;
            int r = idx >> 3, c8 = idx & 7;
            uint32_t off = sw128((uint32_t)(r * 128 + c8 * 16));
            const uint16_t* src = A + (size_t)(bm + r) * 2 * K + c * 64 + c8 * 8;
            cp16(base + off, src);                 // A_hi
            cp16(base + AT + off, src + K);        // A_lo
        }
        // W_hi (+W_lo): 128 rows x 8 = 1024 cp16 -> 2/thread
#pragma unroll
        for (int t = 0; t < 2; t++) {
            int idx = tid + t * 512;
            int r = idx >> 3, c8 = idx & 7;
            uint32_t off = sw128((uint32_t)(r * 128 + c8 * 16));
            const uint16_t* src = W + (size_t)(bn + r) * wstride + c * 64 + c8 * 8;
            cp16(base + 2 * AT + off, src);
            if (TERMS == 3) cp16(base + 2 * AT + WT + off, src + K);
        }
        asm volatile("cp.async.commit_group;" ::: "memory");
    };

    const int ar = wm * 64 + (lane & 15);
    const int br = wn * 32 + (lane & 15);
    const uint32_t kh = (uint32_t)((lane >> 4) * 16);

    uint32_t arsw[MI], brsw[NF / 2];
#pragma unroll
    for (int mi = 0; mi < MI; mi++) arsw[mi] = sw128((uint32_t)((ar + 16 * mi) * 128));
#pragma unroll
    for (int p = 0; p < NF / 2; p++) brsw[p] = sw128((uint32_t)((br + 16 * p) * 128));

    load_stage(0, 0);
    int buf = 0;
    for (int c = 0; c < nc; c++) {
        if (c + 1 < nc) {
            load_stage(c + 1, buf ^ 1);
            asm volatile("cp.async.wait_group 1;" ::: "memory");
        } else {
            asm volatile("cp.async.wait_group 0;" ::: "memory");
        }
        __syncthreads();

        const uint32_t base = sbase + (uint32_t)buf * STAGE;
#pragma unroll
        for (int ks = 0; ks < 4; ks++) {
            const uint32_t kcol = (uint32_t)(ks * 32) + kh;
            // a_hi + w_hi -> term 1
            uint32_t ah[MI][4];
#pragma unroll
            for (int mi = 0; mi < MI; mi++)
                ldsm4(ah[mi][0], ah[mi][1], ah[mi][2], ah[mi][3],
                      base + (arsw[mi] ^ kcol));
            uint32_t bh[NF][2];
#pragma unroll
            for (int p = 0; p < NF / 2; p++) {
                uint32_t r0, r1, r2, r3;
                ldsm4(r0, r1, r2, r3, base + 2 * AT + (brsw[p] ^ kcol));
                bh[2 * p][0] = r0; bh[2 * p][1] = r2;
                bh[2 * p + 1][0] = r1; bh[2 * p + 1][1] = r3;
            }
#pragma unroll
            for (int mi = 0; mi < MI; mi++)
#pragma unroll
                for (int nf = 0; nf < NF; nf++) {
                    if (FP16) mma_f16(acc[mi][nf], ah[mi][0], ah[mi][1], ah[mi][2], ah[mi][3], bh[nf][0], bh[nf][1]);
                    else      mma_bf16(acc[mi][nf], ah[mi][0], ah[mi][1], ah[mi][2], ah[mi][3], bh[nf][0], bh[nf][1]);
                }
            if (TERMS == 3) {
                // term 2: a_hi * w_lo (a_hi reused)
                uint32_t bl[NF][2];
#pragma unroll
                for (int p = 0; p < NF / 2; p++) {
                    uint32_t r0, r1, r2, r3;
                    ldsm4(r0, r1, r2, r3, base + 2 * AT + WT + (brsw[p] ^ kcol));
                    bl[2 * p][0] = r0; bl[2 * p][1] = r2;
                    bl[2 * p + 1][0] = r1; bl[2 * p + 1][1] = r3;
                }
#pragma unroll
                for (int mi = 0; mi < MI; mi++)
#pragma unroll
                    for (int nf = 0; nf < NF; nf++)
                        mma_bf16(acc[mi][nf], ah[mi][0], ah[mi][1], ah[mi][2], ah[mi][3], bl[nf][0], bl[nf][1]);
            }
            // term 3 (or 2 for fp16): a_lo * w_hi (w_hi reused)
            uint32_t al[MI][4];
#pragma unroll
            for (int mi = 0; mi < MI; mi++)
                ldsm4(al[mi][0], al[mi][1], al[mi][2], al[mi][3],
                      base + AT + (arsw[mi] ^ kcol));
#pragma unroll
            for (int mi = 0; mi < MI; mi++)
#pragma unroll
                for (int nf = 0; nf < NF; nf++) {
                    if (FP16) mma_f16(acc[mi][nf], al[mi][0], al[mi][1], al[mi][2], al[mi][3], bh[nf][0], bh[nf][1]);
                    else      mma_bf16(acc[mi][nf], al[mi][0], al[mi][1], al[mi][2], al[mi][3], bh[nf][0], bh[nf][1]);
                }
        }
        __syncthreads();
        buf ^= 1;
    }

    // ---- epilogue ----
    const int row0 = bm + wm * 64 + (lane >> 2);
    const int colb = bn + wn * 32 + (lane & 3) * 2;
#pragma unroll
    for (int mi = 0; mi < MI; mi++) {
#pragma unroll
        for (int nf = 0; nf < NF; nf++) {
            const int col = colb + nf * 8;
            const float b0 = bias[col], b1 = bias[col + 1];
#pragma unroll
            for (int h = 0; h < 2; h++) {
                const int m = row0 + mi * 16 + h * 8;
                float v0 = acc[mi][nf][2 * h + 0] + b0;
                float v1 = acc[mi][nf][2 * h + 1] + b1;
                if (MODE == 0) {
                    float2 o; o.x = v0; o.y = v1;
                    *(float2*)((float*)Cout + (size_t)m * N + col) = o;
                } else if (MODE == 1 && FP16) {
                    v0 = selu_f(v0); v1 = selu_f(v1);
                    __half h0, l0, h1, l1;
                    split2h(v0, h0, l0); split2h(v1, h1, l1);
                    __half* C = (__half*)Cout;
                    const size_t base2 = (size_t)m * (2 * (size_t)N) + col;
                    *(uint32_t*)(C + base2)     = pack_h2(h0, h1);
                    *(uint32_t*)(C + base2 + N) = pack_h2(l0, l1);
                } else if (MODE == 1) {        // bf16 3-plane (for e3-old consumer)
                    v0 = selu_f(v0); v1 = selu_f(v1);
                    __nv_bfloat16 h0, l0, h1, l1;
                    split2(v0, h0, l0); split2(v1, h1, l1);
                    uint32_t hh = pack_bf2(h0, h1), ll = pack_bf2(l0, l1);
                    __nv_bfloat16* C = (__nv_bfloat16*)Cout;
                    const size_t base3 = (size_t)m * (3 * (size_t)N) + col;
                    *(uint32_t*)(C + base3)         = hh;
                    *(uint32_t*)(C + base3 + N)     = hh;
                    *(uint32_t*)(C + base3 + 2 * N) = ll;
                } else {                        // MODE 3: bf16 2-plane
                    v0 = selu_f(v0); v1 = selu_f(v1);
                    __nv_bfloat16 h0, l0, h1, l1;
                    split2(v0, h0, l0); split2(v1, h1, l1);
                    __nv_bfloat16* C = (__nv_bfloat16*)Cout;
                    const size_t base2 = (size_t)m * (2 * (size_t)N) + col;
                    *(uint32_t*)(C + base2)     = pack_bf2(h0, h1);
                    *(uint32_t*)(C + base2 + N) = pack_bf2(l0, l1);
                }
            }
        }
    }
}

// ================= old-style GEMM (e3 + lp fallback) =================
// 256 threads, 8 warps 4x2, BM x BN, 3-stage. MODE 0: fp32+bias. MODE 2: -0.5*acc.
template<int BM, int BN, int MODE>
__global__ void __launch_bounds__(256) mma_gemm(
    const void* __restrict__ Ain, const void* __restrict__ Win,
    const float* __restrict__ bias, void* __restrict__ Cout,
    int N, int KX)
{
    if (MODE == 2 && g_ident) return;

    constexpr int ABYTES = BM * 128;
    constexpr int BBYTES = BN * 128;
    constexpr int BUF = ABYTES + BBYTES;
    constexpr int NF = BN / 16;
    constexpr int WR = BM / 4;
    constexpr int MI = (WR >= 16) ? (WR / 16) : 1;

    const uint16_t* A = (const uint16_t*)Ain;
    const uint16_t* W = (const uint16_t*)Win;

    extern __shared__ __align__(1024) char smem[];
    const uint32_t sbase = smem_u32(smem);

    const int tid = threadIdx.x;
    const int lane = tid & 31;
    const int wid = tid >> 5;
    const int wm = wid & 3;
    const int wn = wid >> 2;
    const int bm = blockIdx.y * BM;
    const int bn = blockIdx.x * BN;

    float acc[MI][NF][4];
#pragma unroll
    for (int i = 0; i < MI; i++)
#pragma unroll
        for (int j = 0; j < NF; j++)
#pragma unroll
            for (int c = 0; c < 4; c++) acc[i][j][c] = 0.f;

    const int nk = KX >> 6;

    auto load_tile = [&](int ck, int b) {
        const uint32_t aB = sbase + (uint32_t)b * BUF;
        const uint32_t bB = aB + ABYTES;
        const uint16_t* Ap = A + (size_t)bm * KX + ck * 64;
        const uint16_t* Wq = W + (size_t)bn * KX + ck * 64;
#pragma unroll
        for (int t = 0; t < (BM * 8) / 256; t++) {
            int idx = tid + t * 256;
            int r = idx >> 3, c = idx & 7;
            cp16(aB + sw128((uint32_t)(r * 128 + c * 16)), Ap + (size_t)r * KX + c * 8);
        }
#pragma unroll
        for (int t = 0; t < (BN * 8) / 256; t++) {
            int idx = tid + t * 256;
            int r = idx >> 3, c = idx & 7;
            cp16(bB + sw128((uint32_t)(r * 128 + c * 16)), Wq + (size_t)r * KX + c * 8);
        }
        asm volatile("cp.async.commit_group;" ::: "memory");
    };

    const int ar = wm * WR + (lane & 15);
    const int br = wn * (BN / 2) + (lane & 15);
    const uint32_t kh = (uint32_t)((lane >> 4) * 16);

    uint32_t arsw[MI], brsw[NF / 2];
#pragma unroll
    for (int mi = 0; mi < MI; mi++) arsw[mi] = sw128((uint32_t)((ar + 16 * mi) * 128));
#pragma unroll
    for (int p = 0; p < NF / 2; p++) brsw[p] = sw128((uint32_t)((br + 16 * p) * 128));

    load_tile(0, 0);
    if (nk > 1) load_tile(1, 1);

    int buf = 0;
    for (int ck = 0; ck < nk; ck++) {
        if (ck < nk - 1) asm volatile("cp.async.wait_group 1;" ::: "memory");
        else             asm volatile("cp.async.wait_group 0;" ::: "memory");
        __syncthreads();
        if (ck + 2 < nk) {
            int nb = buf + 2; if (nb >= 3) nb -= 3;
            load_tile(ck + 2, nb);
        }

        const uint32_t aB = sbase + (uint32_t)buf * BUF;
        const uint32_t bB = aB + ABYTES;
#pragma unroll
        for (int ks = 0; ks < 4; ks++) {
            const uint32_t kcol = (uint32_t)(ks * 32) + kh;
            uint32_t a[MI][4];
#pragma unroll
            for (int mi = 0; mi < MI; mi++)
                ldsm4(a[mi][0], a[mi][1], a[mi][2], a[mi][3], aB + (arsw[mi] ^ kcol));
            uint32_t bf[NF][2];
#pragma unroll
            for (int p = 0; p < NF / 2; p++) {
                uint32_t r0, r1, r2, r3;
                ldsm4(r0, r1, r2, r3, bB + (brsw[p] ^ kcol));
                bf[2 * p][0] = r0; bf[2 * p][1] = r2;
                bf[2 * p + 1][0] = r1; bf[2 * p + 1][1] = r3;
            }
#pragma unroll
            for (int mi = 0; mi < MI; mi++)
#pragma unroll
                for (int nf = 0; nf < NF; nf++)
                    mma_bf16(acc[mi][nf], a[mi][0], a[mi][1], a[mi][2], a[mi][3],
                             bf[nf][0], bf[nf][1]);
        }
        buf++; if (buf == 3) buf = 0;
    }

    const int row0 = bm + wm * WR + (lane >> 2);
    const int colb = bn + wn * (BN / 2) + (lane & 3) * 2;
#pragma unroll
    for (int mi = 0; mi < MI; mi++) {
#pragma unroll
        for (int nf = 0; nf < NF; nf++) {
            const int col = colb + nf * 8;
            float b0 = 0.f, b1 = 0.f;
            if (MODE != 2) { b0 = bias[col]; b1 = bias[col + 1]; }
#pragma unroll
            for (int h = 0; h < 2; h++) {
                const int m = row0 + mi * 16 + h * 8;
                float v0 = acc[mi][nf][2 * h + 0] + b0;
                float v1 = acc[mi][nf][2 * h + 1] + b1;
                if (MODE == 0) {
                    float2 o; o.x = v0; o.y = v1;
                    *(float2*)((float*)Cout + (size_t)m * N + col) = o;
                } else {
                    float2 o; o.x = -0.5f * v0; o.y = -0.5f * v1;
                    *(float2*)((float*)Cout + (size_t)m * N + col) = o;
                }
            }
        }
    }
}

// ---------------- Cholesky (+ inverse & logdet) — exact fp32 ----------------
__global__ void chol_kernel(const float* __restrict__ cov) {
    __shared__ float Ls[EMB][EMB + 1];
    __shared__ float Inv[EMB][EMB + 1];
    const int k = blockIdx.x & (KC - 1);
    const bool raw = blockIdx.x >= KC;
    const int i = threadIdx.x;
    const float* A = cov + (size_t)k * EMB * EMB;
    for (int j = 0; j < EMB; j++) Ls[i][j] = A[i * EMB + j];
    if (!raw) Ls[i][i] += 0.005f;
    __syncthreads();
    for (int j = 0; j < EMB; j++) {
        if (i == j) {
            float s = Ls[j][j];
            for (int t = 0; t < j; t++) s -= Ls[j][t] * Ls[j][t];
            Ls[j][j] = sqrtf(s);
        }
        __syncthreads();
        if (i > j) {
            float s = Ls[i][j];
            for (int t = 0; t < j; t++) s -= Ls[i][t] * Ls[j][t];
            Ls[i][j] = s / Ls[j][j];
        }
        __syncthreads();
    }
    if (raw) {
        float* out = g_Lraw + (size_t)k * EMB * EMB;
        for (int j = 0; j < EMB; j++) out[i * EMB + j] = (j <= i) ? Ls[i][j] : 0.f;
    } else {
        if (i == 0) {
            float ld = 0.f;
            for (int t = 0; t < EMB; t++) ld += logf(Ls[t][t]);
            g_logdet[k] = 2.f * ld;
        }
        const int c = i;
        for (int r = 0; r < EMB; r++) {
            if (r < c) { Inv[r][c] = 0.f; continue; }
            float s = (r == c) ? 1.f : 0.f;
            for (int t = c; t < r; t++) s -= Ls[r][t] * Inv[t][c];
            Inv[r][c] = s / Ls[r][r];
        }
        __syncthreads();
        float* out = g_Linv + (size_t)k * EMB * EMB;
        for (int j = 0; j < EMB; j++) out[i * EMB + j] = Inv[i][j];
    }
}

// ---------------- identity detection ----------------
__global__ void ident_init_kernel() {
    if (threadIdx.x == 0 && blockIdx.x == 0) g_ident = 1;
}
__global__ void ident_check_kernel() {
    const int k = blockIdx.x;
    const int i = threadIdx.x;
    const float gamma = g_Linv[0];
    const float* L = g_Linv + (size_t)k * EMB * EMB + (size_t)i * EMB;
    bool ok = true;
    for (int j = 0; j < EMB; j++) {
        float v = L[j];
        if (j == i) { if (v != gamma) ok = false; }
        else        { if (v != 0.0f)  ok = false; }
    }
    if (!__syncthreads_and(ok ? 1 : 0)) {
        if (i == 0) atomicAnd(&g_ident, 0);
    }
}

// ---------------- identity fast-path lp ----------------
__global__ void __launch_bounds__(128) ident_lp_kernel(
    const float* __restrict__ means, const float* __restrict__ sizes,
    float* __restrict__ lp)
{
    if (!g_ident) return;
    __shared__ float es[64][EMB];
    const int k = blockIdx.y * 128 + threadIdx.x;
    const int b0 = blockIdx.x * 64;
    const float gamma = g_Linv[0];
    const float g2 = gamma * gamma;

    float mu[EMB];
#pragma unroll
    for (int j = 0; j < EMB; j++) mu[j] = means[k * EMB + j];
    const float ck = logf(sizes[k]) - 0.5f * (64.f * LOG2PI_F + g_logdet[k]);

    for (int t = threadIdx.x; t < 64 * EMB / 4; t += 128) {
        int bb = t / (EMB / 4), jj = t % (EMB / 4);
        ((float4*)es[bb])[jj] = ((const float4*)(g_enc + (size_t)(b0 + bb) * EMB))[jj];
    }
    __syncthreads();

    for (int bb = 0; bb < 64; bb++) {
        float q = 0.f;
#pragma unroll
        for (int j = 0; j < EMB; j++) {
            float d = es[bb][j] - mu[j];
            q = fmaf(d, d, q);
        }
        lp[(size_t)(b0 + bb) * KC + k] = ck - 0.5f * g2 * q;
    }
}

// ---------------- Wp build (general path) ----------------
__global__ void __launch_bounds__(128) wp_build_kernel(
    const float* __restrict__ means, const float* __restrict__ sizes)
{
    if (g_ident) return;
    __shared__ float L[EMB * EMB];
    __shared__ float P[EMB * (EMB + 1)];
    __shared__ float pm[EMB];
    __shared__ float mu[EMB];
    __shared__ float ck;
    const int k = blockIdx.x;
    const int tid = threadIdx.x;

    for (int i = tid; i < (EMB * EMB) / 4; i += 128)
        ((float4*)L)[i] = ((const float4*)(g_Linv + (size_t)k * EMB * EMB))[i];
    if (tid < EMB) mu[tid] = means[k * EMB + tid];
    __syncthreads();

    for (int idx = tid; idx < EMB * EMB; idx += 128) {
        int i = idx >> 6, c = idx & 63;
        float s = 0.f;
        for (int d = 0; d < EMB; d++) s += L[d * EMB + i] * L[d * EMB + c];
        P[i * (EMB + 1) + c] = s;
    }
    __syncthreads();
    if (tid < EMB) {
        float s = 0.f;
        for (int j = 0; j < EMB; j++) s += P[tid * (EMB + 1) + j] * mu[j];
        pm[tid] = s;
    }
    __syncthreads();
    if (tid == 0) {
        float s = 0.f;
        for (int i = 0; i < EMB; i++) s += pm[i] * mu[i];
        ck = s + g_logdet[k] + 64.f * LOG2PI_F - 2.f * logf(sizes[k]);
    }
    __syncthreads();

    __nv_bfloat16* out = g_Wp + (size_t)k * K3Q;
    for (int t = tid; t < NFEAT; t += 128) {
        float w;
        if (t < NTRI) {
            int i, j; tri_ij(t, i, j);
            w = P[i * (EMB + 1) + j] * (i == j ? 1.f : 2.f);
        } else if (t < NTRI + EMB) {
            w = -2.f * pm[t - NTRI];
        } else if (t == NTRI + EMB) {
            w = ck;
        } else w = 0.f;
        __nv_bfloat16 h, l; split2(w, h, l);
        out[t] = h; out[NFEAT + t] = l; out[2 * NFEAT + t] = h;
    }
}

// ---------------- G build (general path) ----------------
__global__ void __launch_bounds__(256) g_build_kernel() {
    if (g_ident) return;
    __shared__ float e[EMB];
    const int b = blockIdx.x;
    const int tid = threadIdx.x;
    if (tid < EMB) e[tid] = g_enc[(size_t)b * EMB + tid];
    __syncthreads();
    __nv_bfloat16* out = g_Gs + (size_t)b * K3Q;
    for (int t = tid; t < NFEAT; t += 256) {
        float v;
        if (t < NTRI) {
            int i, j; tri_ij(t, i, j);
            v = e[i] * e[j];
        } else if (t < NTRI + EMB) {
            v = e[t - NTRI];
        } else if (t == NTRI + EMB) {
            v = 1.f;
        } else v = 0.f;
        __nv_bfloat16 h, l; split2(v, h, l);
        out[t] = h; out[NFEAT + t] = h; out[2 * NFEAT + t] = l;
    }
}

// ---------------- top-2 ----------------
__global__ void top2_kernel(const float* __restrict__ lp) {
    int row = (blockIdx.x * blockDim.x + threadIdx.x) >> 5;
    int lane = threadIdx.x & 31;
    if (row >= BATCH) return;
    const float* r = lp + (size_t)row * KC;

    float b1 = -INFINITY; int i1 = 0;
    for (int k = lane; k < KC; k += 32) {
        float v = r[k];
        if (v > b1 || (v == b1 && k < i1)) { b1 = v; i1 = k; }
    }
#pragma unroll
    for (int off = 16; off; off >>= 1) {
        float ov = __shfl_down_sync(0xffffffffu, b1, off);
        int   oi = __shfl_down_sync(0xffffffffu, i1, off);
        if (ov > b1 || (ov == b1 && oi < i1)) { b1 = ov; i1 = oi; }
    }
    b1 = __shfl_sync(0xffffffffu, b1, 0);
    i1 = __shfl_sync(0xffffffffu, i1, 0);

    float b2 = -INFINITY; int i2 = (i1 == 0) ? 1 : 0;
    for (int k = lane; k < KC; k += 32) {
        if (k == i1) continue;
        float v = r[k];
        if (v > b2 || (v == b2 && k < i2)) { b2 = v; i2 = k; }
    }
#pragma unroll
    for (int off = 16; off; off >>= 1) {
        float ov = __shfl_down_sync(0xffffffffu, b2, off);
        int   oi = __shfl_down_sync(0xffffffffu, i2, off);
        if (ov > b2 || (ov == b2 && oi < i2)) { b2 = ov; i2 = oi; }
    }
    if (lane == 0) { int2 t; t.x = i1; t.y = i2; g_top2[row] = t; }
}

// ---------------- exact fp32 refine ----------------
__global__ void refine_kernel(const float* __restrict__ means, const float* __restrict__ sizes) {
    int row = (blockIdx.x * blockDim.x + threadIdx.x) >> 5;
    int lane = threadIdx.x & 31;
    if (row >= BATCH) return;
    int2 cand = g_top2[row];

    float e0 = g_enc[(size_t)row * EMB + lane];
    float e1 = g_enc[(size_t)row * EMB + 32 + lane];

    float lp[2];
#pragma unroll
    for (int c = 0; c < 2; c++) {
        int k = c ? cand.y : cand.x;
        float d0 = e0 - means[k * EMB + lane];
        float d1 = e1 - means[k * EMB + 32 + lane];
        const float* L = g_Linv + (size_t)k * EMB * EMB;
        float s0 = 0.f, s1 = 0.f;
#pragma unroll 8
        for (int j = 0; j < 32; j++) {
            float dv = __shfl_sync(0xffffffffu, d0, j);
            s0 += L[lane * EMB + j] * dv;
            s1 += L[(lane + 32) * EMB + j] * dv;
        }
#pragma unroll 8
        for (int j = 0; j < 32; j++) {
            float dv = __shfl_sync(0xffffffffu, d1, j);
            s0 += L[lane * EMB + 32 + j] * dv;
            s1 += L[(lane + 32) * EMB + 32 + j] * dv;
        }
        float q = s0 * s0 + s1 * s1;
#pragma unroll
        for (int off = 16; off; off >>= 1) q += __shfl_down_sync(0xffffffffu, q, off);
        if (lane == 0)
            lp[c] = logf(sizes[k]) - 0.5f * (64.f * LOG2PI_F + g_logdet[k]) - 0.5f * q;
    }
    if (lane == 0) {
        int best = cand.x;
        if (lp[1] > lp[0] || (lp[1] == lp[0] && cand.y < cand.x)) best = cand.y;
        g_idx[row] = best;
    }
}

// ---------------- sample -> split-2 fp16 ----------------
__global__ void __launch_bounds__(64) sample_kernel(
    const float* __restrict__ noise, const float* __restrict__ means)
{
    __shared__ float sL[EMB * EMB];
    __shared__ float sn[EMB];
    const int b = blockIdx.x;
    const int t = threadIdx.x;
    const int k = g_idx[b];
    const float* L = g_Lraw + (size_t)k * EMB * EMB;
    for (int i = t; i < (EMB * EMB) / 4; i += 64)
        ((float4*)sL)[i] = ((const float4*)L)[i];
    sn[t] = noise[(size_t)b * EMB + t];
    __syncthreads();
    float s = means[k * EMB + t];
    for (int j = 0; j <= t; j++) s += sL[t * EMB + j] * sn[j];
    __half h, l; split2h(s, h, l);
    size_t base = (size_t)b * 2 * EMB;
    g_qs[base + t] = h; g_qs[base + EMB + t] = l;
}

// ---------------- pack idx ----------------
__global__ void pack_kernel(float* __restrict__ out, int out_size) {
    int i = blockIdx.x * blockDim.x + threadIdx.x;
    if (out_size >= IDX_OFF + BATCH && i < BATCH)
        out[IDX_OFF + i] = (float)g_idx[i];
}

// ---------------- launch ----------------
extern "C" void kernel_launch(void* const* d_in, const int* in_sizes, int n_in,
                              void* d_out, int out_size)
{
    const float* x   = (const float*)d_in[0];
    const float* noi = (const float*)d_in[1];
    const float* eW1 = (const float*)d_in[2];
    const float* eb1 = (const float*)d_in[3];
    const float* eW2 = (const float*)d_in[4];
    const float* eb2 = (const float*)d_in[5];
    const float* eW3 = (const float*)d_in[6];
    const float* eb3 = (const float*)d_in[7];
    const float* dW1 = (const float*)d_in[8];
    const float* db1 = (const float*)d_in[9];
    const float* dW2 = (const float*)d_in[10];
    const float* db2 = (const float*)d_in[11];
    const float* dW3 = (const float*)d_in[12];
    const float* db3 = (const float*)d_in[13];
    const float* means = (const float*)d_in[14];
    const float* sizes = (const float*)d_in[15];
    const float* cov   = (const float*)d_in[16];
    float* out = (float*)d_out;

    __nv_bfloat16 *xs, *h1s, *h2s, *ew1s, *ew2s, *ew3s, *gs, *wp;
    __half *qs, *dw1s, *dw2s, *dw3s;
    float *enc;
    cudaGetSymbolAddress((void**)&xs,  g_xs);
    cudaGetSymbolAddress((void**)&h1s, g_h1s);
    cudaGetSymbolAddress((void**)&h2s, g_h2s);
    cudaGetSymbolAddress((void**)&qs,  g_qs);
    cudaGetSymbolAddress((void**)&ew1s, g_eW1s);
    cudaGetSymbolAddress((void**)&ew2s, g_eW2s);
    cudaGetSymbolAddress((void**)&ew3s, g_eW3s);
    cudaGetSymbolAddress((void**)&dw1s, g_dW1s);
    cudaGetSymbolAddress((void**)&dw2s, g_dW2s);
    cudaGetSymbolAddress((void**)&dw3s, g_dW3s);
    cudaGetSymbolAddress((void**)&gs,  g_Gs);
    cudaGetSymbolAddress((void**)&wp,  g_Wp);
    cudaGetSymbolAddress((void**)&enc, g_enc);

    const int SMF3 = 2 * (2 * 256 * 128 + 2 * 128 * 128);   // 196608 (fused TERMS=3)
    const int SMF2 = 2 * (2 * 256 * 128 + 1 * 128 * 128);   // 163840 (fused TERMS=2)
    const int SM128 = 3 * ((128 + 128) * 128);              // 98304 (old, lp fallback)
    const int SM64  = 3 * ((64 + 64) * 128);                // 49152 (old, e3)
    cudaFuncSetAttribute(gemm_fused<3, 3, 0>, cudaFuncAttributeMaxDynamicSharedMemorySize, SMF3);
    cudaFuncSetAttribute(gemm_fused<3, 1, 0>, cudaFuncAttributeMaxDynamicSharedMemorySize, SMF3);
    cudaFuncSetAttribute(gemm_fused<2, 1, 1>, cudaFuncAttributeMaxDynamicSharedMemorySize, SMF2);
    cudaFuncSetAttribute(gemm_fused<2, 0, 1>, cudaFuncAttributeMaxDynamicSharedMemorySize, SMF2);
    cudaFuncSetAttribute(mma_gemm<64, 64, 0>,   cudaFuncAttributeMaxDynamicSharedMemorySize, SM64);
    cudaFuncSetAttribute(mma_gemm<128, 128, 2>, cudaFuncAttributeMaxDynamicSharedMemorySize, SM128);

    // ---- encoder ----
    split2_kernel<<<(BATCH * IN_DIM / 4 + 255) / 256, 256>>>(x, xs, BATCH * IN_DIM, IN_DIM);
    split2_kernel<<<(DENSE * IN_DIM / 4 + 255) / 256, 256>>>(eW1, ew1s, DENSE * IN_DIM, IN_DIM);
    split2_kernel<<<(DENSE * DENSE / 4 + 255) / 256, 256>>>(eW2, ew2s, DENSE * DENSE, DENSE);
    gemm_fused<3, 3, 0><<<dim3(DENSE / 128, BATCH / 256), 512, SMF3>>>(   // e1 -> h1s (2-plane bf16)
        xs, ew1s, eb1, h1s, DENSE, IN_DIM);
    chol_kernel<<<2 * KC, EMB>>>(cov);
    gemm_fused<3, 1, 0><<<dim3(DENSE / 128, BATCH / 256), 512, SMF3>>>(   // e2 -> h2s (3-plane bf16)
        h1s, ew2s, eb2, h2s, DENSE, DENSE);
    ident_init_kernel<<<1, 32>>>();
    ident_check_kernel<<<KC, EMB>>>();
    wp_build_kernel<<<KC, 128>>>(means, sizes);
    split_w_kernel<<<(EMB * DENSE / 4 + 255) / 256, 256>>>(eW3, ew3s, EMB * DENSE, DENSE);
    mma_gemm<64, 64, 0><<<dim3(EMB / 64, BATCH / 64), 256, SM64>>>(       // e3 -> enc (fp32)
        h2s, ew3s, eb3, enc, EMB, 3 * DENSE);

    // ---- GMM log-probs: identity fast path OR tri-feature GEMM ----
    g_build_kernel<<<BATCH, 256>>>();
    mma_gemm<128, 128, 2><<<dim3(KC / 128, BATCH / 128), 256, SM128>>>(
        gs, wp, nullptr, out + LP_OFF, KC, K3Q);
    ident_lp_kernel<<<dim3(BATCH / 64, KC / 128), 128>>>(means, sizes, out + LP_OFF);
    top2_kernel<<<(BATCH * 32) / 256, 256>>>(out + LP_OFF);
    refine_kernel<<<(BATCH * 32) / 256, 256>>>(means, sizes);
    sample_kernel<<<BATCH, EMB>>>(noi, means);

    // ---- decoder (fp16 fused-2) ----
    cvt_h_kernel<<<(DENSE * EMB / 4 + 255) / 256, 256>>>(dW1, dw1s, DENSE * EMB);
    cvt_h_kernel<<<(DENSE * DENSE / 4 + 255) / 256, 256>>>(dW2, dw2s, DENSE * DENSE);
    cvt_h_kernel<<<(IN_DIM * DENSE / 4 + 255) / 256, 256>>>(dW3, dw3s, IN_DIM * DENSE);
    gemm_fused<2, 1, 1><<<dim3(DENSE / 128, BATCH / 256), 512, SMF2>>>(   // d1 -> h1s (2-plane fp16)
        qs, dw1s, db1, h1s, DENSE, EMB);
    gemm_fused<2, 1, 1><<<dim3(DENSE / 128, BATCH / 256), 512, SMF2>>>(   // d2 -> h2s (2-plane fp16)
        h1s, dw2s, db2, h2s, DENSE, DENSE);
    gemm_fused<2, 0, 1><<<dim3(IN_DIM / 128, BATCH / 256), 512, SMF2>>>(  // d3 -> out (fp32)
        h2s, dw3s, db3, out, IN_DIM, DENSE);

    pack_kernel<<<(BATCH + 255) / 256, 256>>>(out, out_size);
}

// round 14
// speedup vs baseline: 1.4033x; 1.4033x over previous
#include <cuda_runtime.h>
#include <cuda_bf16.h>
#include <cuda_fp16.h>
#include <math.h>
#include <stdint.h>

#define BATCH   8192
#define IN_DIM  512
#define EMB     64
#define KC      256
#define DENSE   1152
#define NTRI    2080
#define NFEAT   2176
#define K3Q     (3*NFEAT)
#define LP_OFF  (BATCH*IN_DIM)
#define IDX_OFF (LP_OFF + BATCH*KC)
#define LOG2PI_F 1.8378770664093453f

// ---------------- scratch ----------------
__device__ __align__(128) __nv_bfloat16 g_xs  [BATCH * 3 * IN_DIM];
__device__ __align__(128) __nv_bfloat16 g_h1s [BATCH * 3 * DENSE];
__device__ __align__(128) __nv_bfloat16 g_h2s [BATCH * 3 * DENSE];
__device__ __align__(128) __half        g_qs  [BATCH * 2 * EMB];
__device__ __align__(128) __nv_bfloat16 g_eW1s[DENSE * 3 * IN_DIM];
__device__ __align__(128) __nv_bfloat16 g_eW2s[DENSE * 3 * DENSE];
__device__ __align__(128) __nv_bfloat16 g_eW3s[EMB   * 3 * DENSE];
__device__ __align__(128) __half        g_dW1s[DENSE * 2 * EMB];
__device__ __align__(128) __half        g_dW2s[DENSE * 2 * DENSE];
__device__ __align__(128) __half        g_dW3s[IN_DIM* 2 * DENSE];
__device__ __align__(128) __nv_bfloat16 g_Gs  [(size_t)BATCH * K3Q];
__device__ __align__(128) __nv_bfloat16 g_Wp  [(size_t)KC * K3Q];
__device__ float g_enc [BATCH * EMB];
__device__ float g_Linv[KC * EMB * EMB];
__device__ float g_Lraw[KC * EMB * EMB];
__device__ float g_logdet[KC];
__device__ int   g_idx [BATCH];
__device__ int2  g_top2[BATCH];
__device__ int   g_ident;       // Linv == gamma*I for all k
__device__ int   g_identraw;    // Lraw == gamma_raw*I for all k

// ---------------- helpers ----------------
__device__ __forceinline__ float selu_f(float x) {
    const float scale = 1.0507009873554805f;
    const float alpha = 1.6732632423543772f;
    return scale * (x > 0.f ? x : alpha * expm1f(x));
}
__device__ __forceinline__ void split2(float v, __nv_bfloat16& hi, __nv_bfloat16& lo) {
    hi = __float2bfloat16(v);
    lo = __float2bfloat16(v - __bfloat162float(hi));
}
__device__ __forceinline__ void split2h(float v, __half& hi, __half& lo) {
    hi = __float2half_rn(v);
    lo = __float2half_rn(v - __half2float(hi));
}
__device__ __forceinline__ uint32_t pack_bf2(__nv_bfloat16 a, __nv_bfloat16 b) {
    __nv_bfloat162 t; t.x = a; t.y = b;
    return *reinterpret_cast<uint32_t*>(&t);
}
__device__ __forceinline__ uint32_t pack_h2(__half a, __half b) {
    __half2 t; t.x = a; t.y = b;
    return *reinterpret_cast<uint32_t*>(&t);
}
__device__ __forceinline__ uint32_t smem_u32(const void* p) {
    uint32_t a;
    asm("{ .reg .u64 t; cvta.to.shared.u64 t, %1; cvt.u32.u64 %0, t; }" : "=r"(a) : "l"(p));
    return a;
}
__device__ __forceinline__ void cp16(uint32_t dst, const void* src) {
    asm volatile("cp.async.cg.shared.global [%0], [%1], 16;" :: "r"(dst), "l"(src));
}
__device__ __forceinline__ uint32_t sw128(uint32_t off) { return off ^ ((off >> 3) & 0x70); }

__device__ __forceinline__ void ldsm4(uint32_t& r0, uint32_t& r1, uint32_t& r2, uint32_t& r3,
                                      uint32_t addr) {
    asm volatile("ldmatrix.sync.aligned.m8n8.x4.shared.b16 {%0,%1,%2,%3}, [%4];"
        : "=r"(r0), "=r"(r1), "=r"(r2), "=r"(r3) : "r"(addr));
}
__device__ __forceinline__ void mma_bf16(float* c,
    uint32_t a0, uint32_t a1, uint32_t a2, uint32_t a3, uint32_t b0, uint32_t b1) {
    asm volatile("mma.sync.aligned.m16n8k16.row.col.f32.bf16.bf16.f32 "
        "{%0,%1,%2,%3}, {%4,%5,%6,%7}, {%8,%9}, {%0,%1,%2,%3};"
        : "+f"(c[0]), "+f"(c[1]), "+f"(c[2]), "+f"(c[3])
        : "r"(a0), "r"(a1), "r"(a2), "r"(a3), "r"(b0), "r"(b1));
}
__device__ __forceinline__ void mma_f16(float* c,
    uint32_t a0, uint32_t a1, uint32_t a2, uint32_t a3, uint32_t b0, uint32_t b1) {
    asm volatile("mma.sync.aligned.m16n8k16.row.col.f32.f16.f16.f32 "
        "{%0,%1,%2,%3}, {%4,%5,%6,%7}, {%8,%9}, {%0,%1,%2,%3};"
        : "+f"(c[0]), "+f"(c[1]), "+f"(c[2]), "+f"(c[3])
        : "r"(a0), "r"(a1), "r"(a2), "r"(a3), "r"(b0), "r"(b1));
}
__device__ __forceinline__ void tri_ij(int t, int& i, int& j) {
    int ii = (int)((sqrtf(8.f * (float)t + 1.f) - 1.f) * 0.5f);
    if ((ii + 1) * (ii + 2) / 2 <= t) ii++;
    if (ii * (ii + 1) / 2 > t) ii--;
    i = ii; j = t - ii * (ii + 1) / 2;
}

// ---------------- split conversions ----------------
__global__ void split_a_kernel(const float* __restrict__ in, __nv_bfloat16* __restrict__ out,
                               int total, int K) {
    int i4 = (blockIdx.x * blockDim.x + threadIdx.x) * 4;
    if (i4 >= total) return;
    int r = i4 / K, c = i4 % K;
    float4 v = *(const float4*)(in + i4);
    __nv_bfloat16 h0, l0, h1, l1, h2, l2, h3, l3;
    split2(v.x, h0, l0); split2(v.y, h1, l1); split2(v.z, h2, l2); split2(v.w, h3, l3);
    uint32_t hA = pack_bf2(h0, h1), hB = pack_bf2(h2, h3);
    uint32_t lA = pack_bf2(l0, l1), lB = pack_bf2(l2, l3);
    size_t b = (size_t)r * 3 * K + c;
    *(uint32_t*)(out + b)         = hA; *(uint32_t*)(out + b + 2)         = hB;
    *(uint32_t*)(out + b + K)     = hA; *(uint32_t*)(out + b + K + 2)     = hB;
    *(uint32_t*)(out + b + 2 * K) = lA; *(uint32_t*)(out + b + 2 * K + 2) = lB;
}
__global__ void split_w_kernel(const float* __restrict__ in, __nv_bfloat16* __restrict__ out,
                               int total, int K) {
    int i4 = (blockIdx.x * blockDim.x + threadIdx.x) * 4;
    if (i4 >= total) return;
    int r = i4 / K, c = i4 % K;
    float4 v = *(const float4*)(in + i4);
    __nv_bfloat16 h0, l0, h1, l1, h2, l2, h3, l3;
    split2(v.x, h0, l0); split2(v.y, h1, l1); split2(v.z, h2, l2); split2(v.w, h3, l3);
    uint32_t hA = pack_bf2(h0, h1), hB = pack_bf2(h2, h3);
    uint32_t lA = pack_bf2(l0, l1), lB = pack_bf2(l2, l3);
    size_t b = (size_t)r * 3 * K + c;
    *(uint32_t*)(out + b)         = hA; *(uint32_t*)(out + b + 2)         = hB;
    *(uint32_t*)(out + b + K)     = lA; *(uint32_t*)(out + b + K + 2)     = lB;
    *(uint32_t*)(out + b + 2 * K) = hA; *(uint32_t*)(out + b + 2 * K + 2) = hB;
}
__global__ void split_wh_kernel(const float* __restrict__ in, __half* __restrict__ out,
                                int total, int K) {
    int i4 = (blockIdx.x * blockDim.x + threadIdx.x) * 4;
    if (i4 >= total) return;
    int r = i4 / K, c = i4 % K;
    float4 v = *(const float4*)(in + i4);
    __half h0 = __float2half_rn(v.x), h1 = __float2half_rn(v.y);
    __half h2 = __float2half_rn(v.z), h3 = __float2half_rn(v.w);
    uint32_t hA = pack_h2(h0, h1), hB = pack_h2(h2, h3);
    size_t b = (size_t)r * 2 * K + c;
    *(uint32_t*)(out + b)     = hA; *(uint32_t*)(out + b + 2)     = hB;
    *(uint32_t*)(out + b + K) = hA; *(uint32_t*)(out + b + K + 2) = hB;
}

// ================= tensor-core GEMM via mma.sync (R12 config) =================
template<int BM, int BN, int STAGES, int MODE, int FP16>
__global__ void __launch_bounds__(256) mma_gemm(
    const void* __restrict__ Ain, const void* __restrict__ Win,
    const float* __restrict__ bias, void* __restrict__ Cout,
    int N, int KX)
{
    if (MODE == 2 && g_ident) return;

    constexpr int ABYTES = BM * 128;
    constexpr int BBYTES = BN * 128;
    constexpr int BUF = ABYTES + BBYTES;
    constexpr int NF = BN / 16;
    constexpr int WR = BM / 4;
    constexpr int MI = (WR >= 16) ? (WR / 16) : 1;

    const uint16_t* A = (const uint16_t*)Ain;
    const uint16_t* W = (const uint16_t*)Win;

    extern __shared__ __align__(1024) char smem[];
    const uint32_t sbase = smem_u32(smem);

    const int tid = threadIdx.x;
    const int lane = tid & 31;
    const int wid = tid >> 5;
    const int wm = wid & 3;
    const int wn = wid >> 2;
    const int bm = blockIdx.y * BM;
    const int bn = blockIdx.x * BN;

    float acc[MI][NF][4];
#pragma unroll
    for (int i = 0; i < MI; i++)
#pragma unroll
        for (int j = 0; j < NF; j++)
#pragma unroll
            for (int c = 0; c < 4; c++) acc[i][j][c] = 0.f;

    const int nk = KX >> 6;

    auto load_tile = [&](int ck, int b) {
        const uint32_t aB = sbase + (uint32_t)b * BUF;
        const uint32_t bB = aB + ABYTES;
        const uint16_t* Ap = A + (size_t)bm * KX + ck * 64;
        const uint16_t* Wq = W + (size_t)bn * KX + ck * 64;
#pragma unroll
        for (int t = 0; t < (BM * 8) / 256; t++) {
            int idx = tid + t * 256;
            int r = idx >> 3, c = idx & 7;
            cp16(aB + sw128((uint32_t)(r * 128 + c * 16)), Ap + (size_t)r * KX + c * 8);
        }
#pragma unroll
        for (int t = 0; t < (BN * 8) / 256; t++) {
            int idx = tid + t * 256;
            int r = idx >> 3, c = idx & 7;
            cp16(bB + sw128((uint32_t)(r * 128 + c * 16)), Wq + (size_t)r * KX + c * 8);
        }
        asm volatile("cp.async.commit_group;" ::: "memory");
    };

    const int ar = wm * WR + (lane & 15);
    const int br = wn * (BN / 2) + (lane & 15);
    const uint32_t kh = (uint32_t)((lane >> 4) * 16);

    uint32_t arsw[MI], brsw[NF / 2];
#pragma unroll
    for (int mi = 0; mi < MI; mi++) arsw[mi] = sw128((uint32_t)((ar + 16 * mi) * 128));
#pragma unroll
    for (int p = 0; p < NF / 2; p++) brsw[p] = sw128((uint32_t)((br + 16 * p) * 128));

    if (STAGES == 3) { load_tile(0, 0); if (nk > 1) load_tile(1, 1); }
    else             { load_tile(0, 0); }

    int buf = 0;
    for (int ck = 0; ck < nk; ck++) {
        if (STAGES == 2) {
            if (ck + 1 < nk) load_tile(ck + 1, buf ^ 1);
            if (ck + 1 < nk) asm volatile("cp.async.wait_group 1;" ::: "memory");
            else             asm volatile("cp.async.wait_group 0;" ::: "memory");
            __syncthreads();
        } else {
            if (ck < nk - 1) asm volatile("cp.async.wait_group 1;" ::: "memory");
            else             asm volatile("cp.async.wait_group 0;" ::: "memory");
            __syncthreads();
            if (ck + 2 < nk) {
                int nb = buf + 2; if (nb >= 3) nb -= 3;
                load_tile(ck + 2, nb);
            }
        }

        const uint32_t aB = sbase + (uint32_t)buf * BUF;
        const uint32_t bB = aB + ABYTES;
#pragma unroll
        for (int ks = 0; ks < 4; ks++) {
            const uint32_t kcol = (uint32_t)(ks * 32) + kh;
            uint32_t a[MI][4];
#pragma unroll
            for (int mi = 0; mi < MI; mi++)
                ldsm4(a[mi][0], a[mi][1], a[mi][2], a[mi][3], aB + (arsw[mi] ^ kcol));
            uint32_t bf[NF][2];
#pragma unroll
            for (int p = 0; p < NF / 2; p++) {
                uint32_t r0, r1, r2, r3;
                ldsm4(r0, r1, r2, r3, bB + (brsw[p] ^ kcol));
                bf[2 * p][0] = r0; bf[2 * p][1] = r2;
                bf[2 * p + 1][0] = r1; bf[2 * p + 1][1] = r3;
            }
#pragma unroll
            for (int mi = 0; mi < MI; mi++)
#pragma unroll
                for (int nf = 0; nf < NF; nf++) {
                    if (FP16) mma_f16(acc[mi][nf], a[mi][0], a[mi][1], a[mi][2], a[mi][3],
                                      bf[nf][0], bf[nf][1]);
                    else      mma_bf16(acc[mi][nf], a[mi][0], a[mi][1], a[mi][2], a[mi][3],
                                       bf[nf][0], bf[nf][1]);
                }
        }
        if (STAGES == 2) __syncthreads();
        buf++; if (buf == STAGES) buf = 0;
    }

    const int row0 = bm + wm * WR + (lane >> 2);
    const int colb = bn + wn * (BN / 2) + (lane & 3) * 2;
#pragma unroll
    for (int mi = 0; mi < MI; mi++) {
#pragma unroll
        for (int nf = 0; nf < NF; nf++) {
            const int col = colb + nf * 8;
            float b0 = 0.f, b1 = 0.f;
            if (MODE != 2) { b0 = bias[col]; b1 = bias[col + 1]; }
#pragma unroll
            for (int h = 0; h < 2; h++) {
                const int m = row0 + mi * 16 + h * 8;
                float v0 = acc[mi][nf][2 * h + 0] + b0;
                float v1 = acc[mi][nf][2 * h + 1] + b1;
                if (MODE == 0) {
                    float2 o; o.x = v0; o.y = v1;
                    *(float2*)((float*)Cout + (size_t)m * N + col) = o;
                } else if (MODE == 2) {
                    float2 o; o.x = -0.5f * v0; o.y = -0.5f * v1;
                    *(float2*)((float*)Cout + (size_t)m * N + col) = o;
                } else if (FP16) {
                    v0 = selu_f(v0); v1 = selu_f(v1);
                    __half h0, l0, h1, l1;
                    split2h(v0, h0, l0); split2h(v1, h1, l1);
                    __half* C = (__half*)Cout;
                    const size_t base = (size_t)m * (2 * (size_t)N) + col;
                    *(uint32_t*)(C + base)     = pack_h2(h0, h1);
                    *(uint32_t*)(C + base + N) = pack_h2(l0, l1);
                } else {
                    v0 = selu_f(v0); v1 = selu_f(v1);
                    __nv_bfloat16 h0, l0, h1, l1;
                    split2(v0, h0, l0); split2(v1, h1, l1);
                    uint32_t hh = pack_bf2(h0, h1);
                    uint32_t ll = pack_bf2(l0, l1);
                    __nv_bfloat16* C = (__nv_bfloat16*)Cout;
                    const size_t base = (size_t)m * (3 * (size_t)N) + col;
                    *(uint32_t*)(C + base)         = hh;
                    *(uint32_t*)(C + base + N)     = hh;
                    *(uint32_t*)(C + base + 2 * N) = ll;
                }
            }
        }
    }
}

// ---------------- Cholesky (+ inverse & logdet) — exact fp32 ----------------
__global__ void chol_kernel(const float* __restrict__ cov) {
    __shared__ float Ls[EMB][EMB + 1];
    __shared__ float Inv[EMB][EMB + 1];
    const int k = blockIdx.x & (KC - 1);
    const bool raw = blockIdx.x >= KC;
    const int i = threadIdx.x;
    const float* A = cov + (size_t)k * EMB * EMB;
    for (int j = 0; j < EMB; j++) Ls[i][j] = A[i * EMB + j];
    if (!raw) Ls[i][i] += 0.005f;
    __syncthreads();
    for (int j = 0; j < EMB; j++) {
        if (i == j) {
            float s = Ls[j][j];
            for (int t = 0; t < j; t++) s -= Ls[j][t] * Ls[j][t];
            Ls[j][j] = sqrtf(s);
        }
        __syncthreads();
        if (i > j) {
            float s = Ls[i][j];
            for (int t = 0; t < j; t++) s -= Ls[i][t] * Ls[j][t];
            Ls[i][j] = s / Ls[j][j];
        }
        __syncthreads();
    }
    if (raw) {
        float* out = g_Lraw + (size_t)k * EMB * EMB;
        for (int j = 0; j < EMB; j++) out[i * EMB + j] = (j <= i) ? Ls[i][j] : 0.f;
    } else {
        if (i == 0) {
            float ld = 0.f;
            for (int t = 0; t < EMB; t++) ld += logf(Ls[t][t]);
            g_logdet[k] = 2.f * ld;
        }
        const int c = i;
        for (int r = 0; r < EMB; r++) {
            if (r < c) { Inv[r][c] = 0.f; continue; }
            float s = (r == c) ? 1.f : 0.f;
            for (int t = c; t < r; t++) s -= Ls[r][t] * Inv[t][c];
            Inv[r][c] = s / Ls[r][r];
        }
        __syncthreads();
        float* out = g_Linv + (size_t)k * EMB * EMB;
        for (int j = 0; j < EMB; j++) out[i * EMB + j] = Inv[i][j];
    }
}

// ---------------- identity detection ----------------
__global__ void ident_init_kernel() {
    if (threadIdx.x == 0 && blockIdx.x == 0) { g_ident = 1; g_identraw = 1; }
}
// RAW=0: check Linv == diag(g_Linv[0]); RAW=1: check Lraw == diag(g_Lraw[0])
template<int RAW>
__global__ void ident_check_kernel() {
    const int k = blockIdx.x;
    const int i = threadIdx.x;
    const float* M = RAW ? g_Lraw : g_Linv;
    const float gamma = M[0];
    const float* L = M + (size_t)k * EMB * EMB + (size_t)i * EMB;
    bool ok = true;
    for (int j = 0; j < EMB; j++) {
        float v = L[j];
        if (j == i) { if (v != gamma) ok = false; }
        else        { if (v != 0.0f)  ok = false; }
    }
    if (!__syncthreads_and(ok ? 1 : 0)) {
        if (i == 0) atomicAnd(RAW ? &g_identraw : &g_ident, 0);
    }
}

// ---------------- identity fast-path lp (exact fp32) ----------------
__global__ void __launch_bounds__(128) ident_lp_kernel(
    const float* __restrict__ means, const float* __restrict__ sizes,
    float* __restrict__ lp)
{
    if (!g_ident) return;
    __shared__ float es[64][EMB];
    const int k = blockIdx.y * 128 + threadIdx.x;
    const int b0 = blockIdx.x * 64;
    const float gamma = g_Linv[0];
    const float g2 = gamma * gamma;

    float mu[EMB];
#pragma unroll
    for (int j = 0; j < EMB; j++) mu[j] = means[k * EMB + j];
    const float ck = logf(sizes[k]) - 0.5f * (64.f * LOG2PI_F + g_logdet[k]);

    for (int t = threadIdx.x; t < 64 * EMB / 4; t += 128) {
        int bb = t / (EMB / 4), jj = t % (EMB / 4);
        ((float4*)es[bb])[jj] = ((const float4*)(g_enc + (size_t)(b0 + bb) * EMB))[jj];
    }
    __syncthreads();

    for (int bb = 0; bb < 64; bb++) {
        float q = 0.f;
#pragma unroll
        for (int j = 0; j < EMB; j++) {
            float d = es[bb][j] - mu[j];
            q = fmaf(d, d, q);
        }
        lp[(size_t)(b0 + bb) * KC + k] = ck - 0.5f * g2 * q;
    }
}

// ---------------- Wp build (general path) ----------------
__global__ void __launch_bounds__(128) wp_build_kernel(
    const float* __restrict__ means, const float* __restrict__ sizes)
{
    if (g_ident) return;
    __shared__ float L[EMB * EMB];
    __shared__ float P[EMB * (EMB + 1)];
    __shared__ float pm[EMB];
    __shared__ float mu[EMB];
    __shared__ float ck;
    const int k = blockIdx.x;
    const int tid = threadIdx.x;

    for (int i = tid; i < (EMB * EMB) / 4; i += 128)
        ((float4*)L)[i] = ((const float4*)(g_Linv + (size_t)k * EMB * EMB))[i];
    if (tid < EMB) mu[tid] = means[k * EMB + tid];
    __syncthreads();

    for (int idx = tid; idx < EMB * EMB; idx += 128) {
        int i = idx >> 6, c = idx & 63;
        float s = 0.f;
        for (int d = 0; d < EMB; d++) s += L[d * EMB + i] * L[d * EMB + c];
        P[i * (EMB + 1) + c] = s;
    }
    __syncthreads();
    if (tid < EMB) {
        float s = 0.f;
        for (int j = 0; j < EMB; j++) s += P[tid * (EMB + 1) + j] * mu[j];
        pm[tid] = s;
    }
    __syncthreads();
    if (tid == 0) {
        float s = 0.f;
        for (int i = 0; i < EMB; i++) s += pm[i] * mu[i];
        ck = s + g_logdet[k] + 64.f * LOG2PI_F - 2.f * logf(sizes[k]);
    }
    __syncthreads();

    __nv_bfloat16* out = g_Wp + (size_t)k * K3Q;
    for (int t = tid; t < NFEAT; t += 128) {
        float w;
        if (t < NTRI) {
            int i, j; tri_ij(t, i, j);
            w = P[i * (EMB + 1) + j] * (i == j ? 1.f : 2.f);
        } else if (t < NTRI + EMB) {
            w = -2.f * pm[t - NTRI];
        } else if (t == NTRI + EMB) {
            w = ck;
        } else w = 0.f;
        __nv_bfloat16 h, l; split2(w, h, l);
        out[t] = h; out[NFEAT + t] = l; out[2 * NFEAT + t] = h;
    }
}

// ---------------- G build (general path) ----------------
__global__ void __launch_bounds__(256) g_build_kernel() {
    if (g_ident) return;
    __shared__ float e[EMB];
    const int b = blockIdx.x;
    const int tid = threadIdx.x;
    if (tid < EMB) e[tid] = g_enc[(size_t)b * EMB + tid];
    __syncthreads();
    __nv_bfloat16* out = g_Gs + (size_t)b * K3Q;
    for (int t = tid; t < NFEAT; t += 256) {
        float v;
        if (t < NTRI) {
            int i, j; tri_ij(t, i, j);
            v = e[i] * e[j];
        } else if (t < NTRI + EMB) {
            v = e[t - NTRI];
        } else if (t == NTRI + EMB) {
            v = 1.f;
        } else v = 0.f;
        __nv_bfloat16 h, l; split2(v, h, l);
        out[t] = h; out[NFEAT + t] = h; out[2 * NFEAT + t] = l;
    }
}

// ---------------- top-2 (writes idx directly when lp is exact) ----------------
__global__ void top2_kernel(const float* __restrict__ lp) {
    int row = (blockIdx.x * blockDim.x + threadIdx.x) >> 5;
    int lane = threadIdx.x & 31;
    if (row >= BATCH) return;
    const float* r = lp + (size_t)row * KC;

    float b1 = -INFINITY; int i1 = 0;
    for (int k = lane; k < KC; k += 32) {
        float v = r[k];
        if (v > b1 || (v == b1 && k < i1)) { b1 = v; i1 = k; }
    }
#pragma unroll
    for (int off = 16; off; off >>= 1) {
        float ov = __shfl_down_sync(0xffffffffu, b1, off);
        int   oi = __shfl_down_sync(0xffffffffu, i1, off);
        if (ov > b1 || (ov == b1 && oi < i1)) { b1 = ov; i1 = oi; }
    }
    b1 = __shfl_sync(0xffffffffu, b1, 0);
    i1 = __shfl_sync(0xffffffffu, i1, 0);

    if (g_ident) {                 // lp exact -> top-1 IS the exact argmax
        if (lane == 0) g_idx[row] = i1;
        return;
    }

    float b2 = -INFINITY; int i2 = (i1 == 0) ? 1 : 0;
    for (int k = lane; k < KC; k += 32) {
        if (k == i1) continue;
        float v = r[k];
        if (v > b2 || (v == b2 && k < i2)) { b2 = v; i2 = k; }
    }
#pragma unroll
    for (int off = 16; off; off >>= 1) {
        float ov = __shfl_down_sync(0xffffffffu, b2, off);
        int   oi = __shfl_down_sync(0xffffffffu, i2, off);
        if (ov > b2 || (ov == b2 && oi < i2)) { b2 = ov; i2 = oi; }
    }
    if (lane == 0) { int2 t; t.x = i1; t.y = i2; g_top2[row] = t; }
}

// ---------------- exact fp32 refine (skipped when lp already exact) ----------------
__global__ void refine_kernel(const float* __restrict__ means, const float* __restrict__ sizes) {
    if (g_ident) return;           // top2_kernel already wrote exact idx
    int row = (blockIdx.x * blockDim.x + threadIdx.x) >> 5;
    int lane = threadIdx.x & 31;
    if (row >= BATCH) return;
    int2 cand = g_top2[row];

    float e0 = g_enc[(size_t)row * EMB + lane];
    float e1 = g_enc[(size_t)row * EMB + 32 + lane];

    float lp[2];
#pragma unroll
    for (int c = 0; c < 2; c++) {
        int k = c ? cand.y : cand.x;
        float d0 = e0 - means[k * EMB + lane];
        float d1 = e1 - means[k * EMB + 32 + lane];
        const float* L = g_Linv + (size_t)k * EMB * EMB;
        float s0 = 0.f, s1 = 0.f;
#pragma unroll 8
        for (int j = 0; j < 32; j++) {
            float dv = __shfl_sync(0xffffffffu, d0, j);
            s0 += L[lane * EMB + j] * dv;
            s1 += L[(lane + 32) * EMB + j] * dv;
        }
#pragma unroll 8
        for (int j = 0; j < 32; j++) {
            float dv = __shfl_sync(0xffffffffu, d1, j);
            s0 += L[lane * EMB + 32 + j] * dv;
            s1 += L[(lane + 32) * EMB + 32 + j] * dv;
        }
        float q = s0 * s0 + s1 * s1;
#pragma unroll
        for (int off = 16; off; off >>= 1) q += __shfl_down_sync(0xffffffffu, q, off);
        if (lane == 0)
            lp[c] = logf(sizes[k]) - 0.5f * (64.f * LOG2PI_F + g_logdet[k]) - 0.5f * q;
    }
    if (lane == 0) {
        int best = cand.x;
        if (lp[1] > lp[0] || (lp[1] == lp[0] && cand.y < cand.x)) best = cand.y;
        g_idx[row] = best;
    }
}

// ---------------- sample -> split-2 fp16 (identity fast path for Lraw) ----------------
__global__ void __launch_bounds__(64) sample_kernel(
    const float* __restrict__ noise, const float* __restrict__ means)
{
    const int b = blockIdx.x;
    const int t = threadIdx.x;
    const int k = g_idx[b];

    if (g_identraw) {
        // Lraw = gamma*I exactly: sample = mean + gamma*noise[t]
        // (bit-identical to the general loop: skipped terms are exact 0*n adds)
        const float gamma = g_Lraw[0];
        float s = means[k * EMB + t] + gamma * noise[(size_t)b * EMB + t];
        __half h, l; split2h(s, h, l);
        size_t base = (size_t)b * 2 * EMB;
        g_qs[base + t] = h; g_qs[base + EMB + t] = l;
        return;
    }

    __shared__ float sL[EMB * EMB];
    __shared__ float sn[EMB];
    const float* L = g_Lraw + (size_t)k * EMB * EMB;
    for (int i = t; i < (EMB * EMB) / 4; i += 64)
        ((float4*)sL)[i] = ((const float4*)L)[i];
    sn[t] = noise[(size_t)b * EMB + t];
    __syncthreads();
    float s = means[k * EMB + t];
    for (int j = 0; j <= t; j++) s += sL[t * EMB + j] * sn[j];
    __half h, l; split2h(s, h, l);
    size_t base = (size_t)b * 2 * EMB;
    g_qs[base + t] = h; g_qs[base + EMB + t] = l;
}

// ---------------- pack idx ----------------
__global__ void pack_kernel(float* __restrict__ out, int out_size) {
    int i = blockIdx.x * blockDim.x + threadIdx.x;
    if (out_size >= IDX_OFF + BATCH && i < BATCH)
        out[IDX_OFF + i] = (float)g_idx[i];
}

// ---------------- launch ----------------
extern "C" void kernel_launch(void* const* d_in, const int* in_sizes, int n_in,
                              void* d_out, int out_size)
{
    const float* x   = (const float*)d_in[0];
    const float* noi = (const float*)d_in[1];
    const float* eW1 = (const float*)d_in[2];
    const float* eb1 = (const float*)d_in[3];
    const float* eW2 = (const float*)d_in[4];
    const float* eb2 = (const float*)d_in[5];
    const float* eW3 = (const float*)d_in[6];
    const float* eb3 = (const float*)d_in[7];
    const float* dW1 = (const float*)d_in[8];
    const float* db1 = (const float*)d_in[9];
    const float* dW2 = (const float*)d_in[10];
    const float* db2 = (const float*)d_in[11];
    const float* dW3 = (const float*)d_in[12];
    const float* db3 = (const float*)d_in[13];
    const float* means = (const float*)d_in[14];
    const float* sizes = (const float*)d_in[15];
    const float* cov   = (const float*)d_in[16];
    float* out = (float*)d_out;

    __nv_bfloat16 *xs, *h1s, *h2s, *ew1s, *ew2s, *ew3s, *gs, *wp;
    __half *qs, *dw1s, *dw2s, *dw3s;
    float *enc;
    cudaGetSymbolAddress((void**)&xs,  g_xs);
    cudaGetSymbolAddress((void**)&h1s, g_h1s);
    cudaGetSymbolAddress((void**)&h2s, g_h2s);
    cudaGetSymbolAddress((void**)&qs,  g_qs);
    cudaGetSymbolAddress((void**)&ew1s, g_eW1s);
    cudaGetSymbolAddress((void**)&ew2s, g_eW2s);
    cudaGetSymbolAddress((void**)&ew3s, g_eW3s);
    cudaGetSymbolAddress((void**)&dw1s, g_dW1s);
    cudaGetSymbolAddress((void**)&dw2s, g_dW2s);
    cudaGetSymbolAddress((void**)&dw3s, g_dW3s);
    cudaGetSymbolAddress((void**)&gs,  g_Gs);
    cudaGetSymbolAddress((void**)&wp,  g_Wp);
    cudaGetSymbolAddress((void**)&enc, g_enc);

    const int SM128 = 3 * ((128 + 128) * 128);   // 98304
    const int SM64  = 3 * ((64 + 64) * 128);     // 49152
    cudaFuncSetAttribute(mma_gemm<128, 128, 3, 1, 0>, cudaFuncAttributeMaxDynamicSharedMemorySize, SM128);
    cudaFuncSetAttribute(mma_gemm<128, 128, 3, 2, 0>, cudaFuncAttributeMaxDynamicSharedMemorySize, SM128);
    cudaFuncSetAttribute(mma_gemm<64, 64, 3, 0, 0>,   cudaFuncAttributeMaxDynamicSharedMemorySize, SM64);
    cudaFuncSetAttribute(mma_gemm<128, 128, 3, 1, 1>, cudaFuncAttributeMaxDynamicSharedMemorySize, SM128);
    cudaFuncSetAttribute(mma_gemm<128, 128, 3, 0, 1>, cudaFuncAttributeMaxDynamicSharedMemorySize, SM128);

    // ---- encoder (bf16 split-3) ----
    split_a_kernel<<<(BATCH * IN_DIM / 4 + 255) / 256, 256>>>(x, xs, BATCH * IN_DIM, IN_DIM);
    split_w_kernel<<<(DENSE * IN_DIM / 4 + 255) / 256, 256>>>(eW1, ew1s, DENSE * IN_DIM, IN_DIM);
    split_w_kernel<<<(DENSE * DENSE / 4 + 255) / 256, 256>>>(eW2, ew2s, DENSE * DENSE, DENSE);
    mma_gemm<128, 128, 3, 1, 0><<<dim3(DENSE / 128, BATCH / 128), 256, SM128>>>(   // #4 profiled
        xs, ew1s, eb1, h1s, DENSE, 3 * IN_DIM);
    chol_kernel<<<2 * KC, EMB>>>(cov);
    mma_gemm<128, 128, 3, 1, 0><<<dim3(DENSE / 128, BATCH / 128), 256, SM128>>>(
        h1s, ew2s, eb2, h2s, DENSE, 3 * DENSE);
    ident_init_kernel<<<1, 32>>>();
    ident_check_kernel<0><<<KC, EMB>>>();
    ident_check_kernel<1><<<KC, EMB>>>();
    wp_build_kernel<<<KC, 128>>>(means, sizes);
    split_w_kernel<<<(EMB * DENSE / 4 + 255) / 256, 256>>>(eW3, ew3s, EMB * DENSE, DENSE);
    mma_gemm<64, 64, 3, 0, 0><<<dim3(EMB / 64, BATCH / 64), 256, SM64>>>(
        h2s, ew3s, eb3, enc, EMB, 3 * DENSE);

    // ---- GMM log-probs: identity fast path OR tri-feature GEMM ----
    g_build_kernel<<<BATCH, 256>>>();
    mma_gemm<128, 128, 3, 2, 0><<<dim3(KC / 128, BATCH / 128), 256, SM128>>>(
        gs, wp, nullptr, out + LP_OFF, KC, K3Q);
    ident_lp_kernel<<<dim3(BATCH / 64, KC / 128), 128>>>(means, sizes, out + LP_OFF);
    top2_kernel<<<(BATCH * 32) / 256, 256>>>(out + LP_OFF);
    refine_kernel<<<(BATCH * 32) / 256, 256>>>(means, sizes);
    sample_kernel<<<BATCH, EMB>>>(noi, means);

    // ---- decoder (fp16 split-2) ----
    split_wh_kernel<<<(DENSE * EMB / 4 + 255) / 256, 256>>>(dW1, dw1s, DENSE * EMB, EMB);
    split_wh_kernel<<<(DENSE * DENSE / 4 + 255) / 256, 256>>>(dW2, dw2s, DENSE * DENSE, DENSE);
    split_wh_kernel<<<(IN_DIM * DENSE / 4 + 255) / 256, 256>>>(dW3, dw3s, IN_DIM * DENSE, DENSE);
    mma_gemm<128, 128, 3, 1, 1><<<dim3(DENSE / 128, BATCH / 128), 256, SM128>>>(
        qs, dw1s, db1, h1s, DENSE, 2 * EMB);
    mma_gemm<128, 128, 3, 1, 1><<<dim3(DENSE / 128, BATCH / 128), 256, SM128>>>(
        h1s, dw2s, db2, h2s, DENSE, 2 * DENSE);
    mma_gemm<128, 128, 3, 0, 1><<<dim3(IN_DIM / 128, BATCH / 128), 256, SM128>>>(
        h2s, dw3s, db3, out, IN_DIM, 2 * DENSE);

    pack_kernel<<<(BATCH + 255) / 256, 256>>>(out, out_size);
}

// round 16
// speedup vs baseline: 1.5975x; 1.1384x over previous
#include <cuda_runtime.h>
#include <cuda_bf16.h>
#include <cuda_fp16.h>
#include <math.h>
#include <stdint.h>

#define BATCH   8192
#define IN_DIM  512
#define EMB     64
#define KC      256
#define DENSE   1152
#define NTRI    2080
#define NFEAT   2176
#define K3Q     (3*NFEAT)
#define LP_OFF  (BATCH*IN_DIM)
#define IDX_OFF (LP_OFF + BATCH*KC)
#define LOG2PI_F 1.8378770664093453f

// ---------------- scratch ----------------
__device__ __align__(128) __nv_bfloat16 g_xs  [BATCH * 3 * IN_DIM];
__device__ __align__(128) __nv_bfloat16 g_h1s [BATCH * 3 * DENSE];   // enc: bf16-3 / dec: fp16-1
__device__ __align__(128) __nv_bfloat16 g_h2s [BATCH * 3 * DENSE];   // enc: bf16-3 / dec: fp16-1
__device__ __align__(128) __half        g_qs  [BATCH * 2 * EMB];
__device__ __align__(128) __nv_bfloat16 g_eW1s[DENSE * 3 * IN_DIM];
__device__ __align__(128) __nv_bfloat16 g_eW2s[DENSE * 3 * DENSE];
__device__ __align__(128) __nv_bfloat16 g_eW3s[EMB   * 3 * DENSE];
__device__ __align__(128) __half        g_dW1s[DENSE * 2 * EMB];     // 2-plane [W|W]
__device__ __align__(128) __half        g_dW2s[DENSE * DENSE];       // 1-plane
__device__ __align__(128) __half        g_dW3s[IN_DIM * DENSE];      // 1-plane
__device__ __align__(128) __nv_bfloat16 g_Gs  [(size_t)BATCH * K3Q];
__device__ __align__(128) __nv_bfloat16 g_Wp  [(size_t)KC * K3Q];
__device__ float g_enc [BATCH * EMB];
__device__ float g_Linv[KC * EMB * EMB];
__device__ float g_Lraw[KC * EMB * EMB];
__device__ float g_logdet[KC];
__device__ int   g_idx [BATCH];
__device__ int2  g_top2[BATCH];
__device__ int   g_ident;       // Linv == gamma*I for all k
__device__ int   g_identraw;    // Lraw == gamma_raw*I for all k

// ---------------- helpers ----------------
__device__ __forceinline__ float selu_f(float x) {
    const float scale = 1.0507009873554805f;
    const float alpha = 1.6732632423543772f;
    return scale * (x > 0.f ? x : alpha * expm1f(x));
}
__device__ __forceinline__ void split2(float v, __nv_bfloat16& hi, __nv_bfloat16& lo) {
    hi = __float2bfloat16(v);
    lo = __float2bfloat16(v - __bfloat162float(hi));
}
__device__ __forceinline__ void split2h(float v, __half& hi, __half& lo) {
    hi = __float2half_rn(v);
    lo = __float2half_rn(v - __half2float(hi));
}
__device__ __forceinline__ uint32_t pack_bf2(__nv_bfloat16 a, __nv_bfloat16 b) {
    __nv_bfloat162 t; t.x = a; t.y = b;
    return *reinterpret_cast<uint32_t*>(&t);
}
__device__ __forceinline__ uint32_t pack_h2(__half a, __half b) {
    __half2 t; t.x = a; t.y = b;
    return *reinterpret_cast<uint32_t*>(&t);
}
__device__ __forceinline__ uint32_t smem_u32(const void* p) {
    uint32_t a;
    asm("{ .reg .u64 t; cvta.to.shared.u64 t, %1; cvt.u32.u64 %0, t; }" : "=r"(a) : "l"(p));
    return a;
}
__device__ __forceinline__ void cp16(uint32_t dst, const void* src) {
    asm volatile("cp.async.cg.shared.global [%0], [%1], 16;" :: "r"(dst), "l"(src));
}
__device__ __forceinline__ uint32_t sw128(uint32_t off) { return off ^ ((off >> 3) & 0x70); }

__device__ __forceinline__ void ldsm4(uint32_t& r0, uint32_t& r1, uint32_t& r2, uint32_t& r3,
                                      uint32_t addr) {
    asm volatile("ldmatrix.sync.aligned.m8n8.x4.shared.b16 {%0,%1,%2,%3}, [%4];"
        : "=r"(r0), "=r"(r1), "=r"(r2), "=r"(r3) : "r"(addr));
}
__device__ __forceinline__ void mma_bf16(float* c,
    uint32_t a0, uint32_t a1, uint32_t a2, uint32_t a3, uint32_t b0, uint32_t b1) {
    asm volatile("mma.sync.aligned.m16n8k16.row.col.f32.bf16.bf16.f32 "
        "{%0,%1,%2,%3}, {%4,%5,%6,%7}, {%8,%9}, {%0,%1,%2,%3};"
        : "+f"(c[0]), "+f"(c[1]), "+f"(c[2]), "+f"(c[3])
        : "r"(a0), "r"(a1), "r"(a2), "r"(a3), "r"(b0), "r"(b1));
}
__device__ __forceinline__ void mma_f16(float* c,
    uint32_t a0, uint32_t a1, uint32_t a2, uint32_t a3, uint32_t b0, uint32_t b1) {
    asm volatile("mma.sync.aligned.m16n8k16.row.col.f32.f16.f16.f32 "
        "{%0,%1,%2,%3}, {%4,%5,%6,%7}, {%8,%9}, {%0,%1,%2,%3};"
        : "+f"(c[0]), "+f"(c[1]), "+f"(c[2]), "+f"(c[3])
        : "r"(a0), "r"(a1), "r"(a2), "r"(a3), "r"(b0), "r"(b1));
}
__device__ __forceinline__ void tri_ij(int t, int& i, int& j) {
    int ii = (int)((sqrtf(8.f * (float)t + 1.f) - 1.f) * 0.5f);
    if ((ii + 1) * (ii + 2) / 2 <= t) ii++;
    if (ii * (ii + 1) / 2 > t) ii--;
    i = ii; j = t - ii * (ii + 1) / 2;
}

// ---------------- split conversions ----------------
__global__ void split_a_kernel(const float* __restrict__ in, __nv_bfloat16* __restrict__ out,
                               int total, int K) {
    int i4 = (blockIdx.x * blockDim.x + threadIdx.x) * 4;
    if (i4 >= total) return;
    int r = i4 / K, c = i4 % K;
    float4 v = *(const float4*)(in + i4);
    __nv_bfloat16 h0, l0, h1, l1, h2, l2, h3, l3;
    split2(v.x, h0, l0); split2(v.y, h1, l1); split2(v.z, h2, l2); split2(v.w, h3, l3);
    uint32_t hA = pack_bf2(h0, h1), hB = pack_bf2(h2, h3);
    uint32_t lA = pack_bf2(l0, l1), lB = pack_bf2(l2, l3);
    size_t b = (size_t)r * 3 * K + c;
    *(uint32_t*)(out + b)         = hA; *(uint32_t*)(out + b + 2)         = hB;
    *(uint32_t*)(out + b + K)     = hA; *(uint32_t*)(out + b + K + 2)     = hB;
    *(uint32_t*)(out + b + 2 * K) = lA; *(uint32_t*)(out + b + 2 * K + 2) = lB;
}
__global__ void split_w_kernel(const float* __restrict__ in, __nv_bfloat16* __restrict__ out,
                               int total, int K) {
    int i4 = (blockIdx.x * blockDim.x + threadIdx.x) * 4;
    if (i4 >= total) return;
    int r = i4 / K, c = i4 % K;
    float4 v = *(const float4*)(in + i4);
    __nv_bfloat16 h0, l0, h1, l1, h2, l2, h3, l3;
    split2(v.x, h0, l0); split2(v.y, h1, l1); split2(v.z, h2, l2); split2(v.w, h3, l3);
    uint32_t hA = pack_bf2(h0, h1), hB = pack_bf2(h2, h3);
    uint32_t lA = pack_bf2(l0, l1), lB = pack_bf2(l2, l3);
    size_t b = (size_t)r * 3 * K + c;
    *(uint32_t*)(out + b)         = hA; *(uint32_t*)(out + b + 2)         = hB;
    *(uint32_t*)(out + b + K)     = lA; *(uint32_t*)(out + b + K + 2)     = lB;
    *(uint32_t*)(out + b + 2 * K) = hA; *(uint32_t*)(out + b + 2 * K + 2) = hB;
}
__global__ void split_wh_kernel(const float* __restrict__ in, __half* __restrict__ out,
                                int total, int K) {
    int i4 = (blockIdx.x * blockDim.x + threadIdx.x) * 4;
    if (i4 >= total) return;
    int r = i4 / K, c = i4 % K;
    float4 v = *(const float4*)(in + i4);
    __half h0 = __float2half_rn(v.x), h1 = __float2half_rn(v.y);
    __half h2 = __float2half_rn(v.z), h3 = __float2half_rn(v.w);
    uint32_t hA = pack_h2(h0, h1), hB = pack_h2(h2, h3);
    size_t b = (size_t)r * 2 * K + c;
    *(uint32_t*)(out + b)     = hA; *(uint32_t*)(out + b + 2)     = hB;
    *(uint32_t*)(out + b + K) = hA; *(uint32_t*)(out + b + K + 2) = hB;
}
// plain fp16 convert (1-plane decoder weights)
__global__ void cvt_h_kernel(const float* __restrict__ in, __half* __restrict__ out, int total) {
    int i4 = (blockIdx.x * blockDim.x + threadIdx.x) * 4;
    if (i4 >= total) return;
    float4 v = *(const float4*)(in + i4);
    *(uint32_t*)(out + i4)     = pack_h2(__float2half_rn(v.x), __float2half_rn(v.y));
    *(uint32_t*)(out + i4 + 2) = pack_h2(__float2half_rn(v.z), __float2half_rn(v.w));
}

// ================= tensor-core GEMM via mma.sync =================
// MODE 0: fp32 +bias. MODE 1: SELU + split out (bf16 3-plane | fp16 2-plane).
// MODE 2: -0.5*acc lp (skipped when g_ident). MODE 4: SELU + fp16 1-plane.
template<int BM, int BN, int STAGES, int MODE, int FP16>
__global__ void __launch_bounds__(256) mma_gemm(
    const void* __restrict__ Ain, const void* __restrict__ Win,
    const float* __restrict__ bias, void* __restrict__ Cout,
    int N, int KX)
{
    if (MODE == 2 && g_ident) return;

    constexpr int ABYTES = BM * 128;
    constexpr int BBYTES = BN * 128;
    constexpr int BUF = ABYTES + BBYTES;
    constexpr int NF = BN / 16;
    constexpr int WR = BM / 4;
    constexpr int MI = (WR >= 16) ? (WR / 16) : 1;

    const uint16_t* A = (const uint16_t*)Ain;
    const uint16_t* W = (const uint16_t*)Win;

    extern __shared__ __align__(1024) char smem[];
    const uint32_t sbase = smem_u32(smem);

    const int tid = threadIdx.x;
    const int lane = tid & 31;
    const int wid = tid >> 5;
    const int wm = wid & 3;
    const int wn = wid >> 2;
    const int bm = blockIdx.y * BM;
    const int bn = blockIdx.x * BN;

    float acc[MI][NF][4];
#pragma unroll
    for (int i = 0; i < MI; i++)
#pragma unroll
        for (int j = 0; j < NF; j++)
#pragma unroll
            for (int c = 0; c < 4; c++) acc[i][j][c] = 0.f;

    const int nk = KX >> 6;

    auto load_tile = [&](int ck, int b) {
        const uint32_t aB = sbase + (uint32_t)b * BUF;
        const uint32_t bB = aB + ABYTES;
        const uint16_t* Ap = A + (size_t)bm * KX + ck * 64;
        const uint16_t* Wq = W + (size_t)bn * KX + ck * 64;
#pragma unroll
        for (int t = 0; t < (BM * 8) / 256; t++) {
            int idx = tid + t * 256;
            int r = idx >> 3, c = idx & 7;
            cp16(aB + sw128((uint32_t)(r * 128 + c * 16)), Ap + (size_t)r * KX + c * 8);
        }
#pragma unroll
        for (int t = 0; t < (BN * 8) / 256; t++) {
            int idx = tid + t * 256;
            int r = idx >> 3, c = idx & 7;
            cp16(bB + sw128((uint32_t)(r * 128 + c * 16)), Wq + (size_t)r * KX + c * 8);
        }
        asm volatile("cp.async.commit_group;" ::: "memory");
    };

    const int ar = wm * WR + (lane & 15);
    const int br = wn * (BN / 2) + (lane & 15);
    const uint32_t kh = (uint32_t)((lane >> 4) * 16);

    uint32_t arsw[MI], brsw[NF / 2];
#pragma unroll
    for (int mi = 0; mi < MI; mi++) arsw[mi] = sw128((uint32_t)((ar + 16 * mi) * 128));
#pragma unroll
    for (int p = 0; p < NF / 2; p++) brsw[p] = sw128((uint32_t)((br + 16 * p) * 128));

    if (STAGES == 3) { load_tile(0, 0); if (nk > 1) load_tile(1, 1); }
    else             { load_tile(0, 0); }

    int buf = 0;
    for (int ck = 0; ck < nk; ck++) {
        if (STAGES == 2) {
            if (ck + 1 < nk) load_tile(ck + 1, buf ^ 1);
            if (ck + 1 < nk) asm volatile("cp.async.wait_group 1;" ::: "memory");
            else             asm volatile("cp.async.wait_group 0;" ::: "memory");
            __syncthreads();
        } else {
            if (ck < nk - 1) asm volatile("cp.async.wait_group 1;" ::: "memory");
            else             asm volatile("cp.async.wait_group 0;" ::: "memory");
            __syncthreads();
            if (ck + 2 < nk) {
                int nb = buf + 2; if (nb >= 3) nb -= 3;
                load_tile(ck + 2, nb);
            }
        }

        const uint32_t aB = sbase + (uint32_t)buf * BUF;
        const uint32_t bB = aB + ABYTES;
#pragma unroll
        for (int ks = 0; ks < 4; ks++) {
            const uint32_t kcol = (uint32_t)(ks * 32) + kh;
            uint32_t a[MI][4];
#pragma unroll
            for (int mi = 0; mi < MI; mi++)
                ldsm4(a[mi][0], a[mi][1], a[mi][2], a[mi][3], aB + (arsw[mi] ^ kcol));
            uint32_t bf[NF][2];
#pragma unroll
            for (int p = 0; p < NF / 2; p++) {
                uint32_t r0, r1, r2, r3;
                ldsm4(r0, r1, r2, r3, bB + (brsw[p] ^ kcol));
                bf[2 * p][0] = r0; bf[2 * p][1] = r2;
                bf[2 * p + 1][0] = r1; bf[2 * p + 1][1] = r3;
            }
#pragma unroll
            for (int mi = 0; mi < MI; mi++)
#pragma unroll
                for (int nf = 0; nf < NF; nf++) {
                    if (FP16) mma_f16(acc[mi][nf], a[mi][0], a[mi][1], a[mi][2], a[mi][3],
                                      bf[nf][0], bf[nf][1]);
                    else      mma_bf16(acc[mi][nf], a[mi][0], a[mi][1], a[mi][2], a[mi][3],
                                       bf[nf][0], bf[nf][1]);
                }
        }
        if (STAGES == 2) __syncthreads();
        buf++; if (buf == STAGES) buf = 0;
    }

    const int row0 = bm + wm * WR + (lane >> 2);
    const int colb = bn + wn * (BN / 2) + (lane & 3) * 2;
#pragma unroll
    for (int mi = 0; mi < MI; mi++) {
#pragma unroll
        for (int nf = 0; nf < NF; nf++) {
            const int col = colb + nf * 8;
            float b0 = 0.f, b1 = 0.f;
            if (MODE != 2) { b0 = bias[col]; b1 = bias[col + 1]; }
#pragma unroll
            for (int h = 0; h < 2; h++) {
                const int m = row0 + mi * 16 + h * 8;
                float v0 = acc[mi][nf][2 * h + 0] + b0;
                float v1 = acc[mi][nf][2 * h + 1] + b1;
                if (MODE == 0) {
                    float2 o; o.x = v0; o.y = v1;
                    *(float2*)((float*)Cout + (size_t)m * N + col) = o;
                } else if (MODE == 2) {
                    float2 o; o.x = -0.5f * v0; o.y = -0.5f * v1;
                    *(float2*)((float*)Cout + (size_t)m * N + col) = o;
                } else if (MODE == 4) {
                    v0 = selu_f(v0); v1 = selu_f(v1);
                    __half* C = (__half*)Cout;
                    *(uint32_t*)(C + (size_t)m * N + col) =
                        pack_h2(__float2half_rn(v0), __float2half_rn(v1));
                } else if (FP16) {
                    v0 = selu_f(v0); v1 = selu_f(v1);
                    __half h0, l0, h1, l1;
                    split2h(v0, h0, l0); split2h(v1, h1, l1);
                    __half* C = (__half*)Cout;
                    const size_t base = (size_t)m * (2 * (size_t)N) + col;
                    *(uint32_t*)(C + base)     = pack_h2(h0, h1);
                    *(uint32_t*)(C + base + N) = pack_h2(l0, l1);
                } else {
                    v0 = selu_f(v0); v1 = selu_f(v1);
                    __nv_bfloat16 h0, l0, h1, l1;
                    split2(v0, h0, l0); split2(v1, h1, l1);
                    uint32_t hh = pack_bf2(h0, h1);
                    uint32_t ll = pack_bf2(l0, l1);
                    __nv_bfloat16* C = (__nv_bfloat16*)Cout;
                    const size_t base = (size_t)m * (3 * (size_t)N) + col;
                    *(uint32_t*)(C + base)         = hh;
                    *(uint32_t*)(C + base + N)     = hh;
                    *(uint32_t*)(C + base + 2 * N) = ll;
                }
            }
        }
    }
}

// ---------------- Cholesky (+ inverse & logdet) — exact fp32 ----------------
__global__ void chol_kernel(const float* __restrict__ cov) {
    __shared__ float Ls[EMB][EMB + 1];
    __shared__ float Inv[EMB][EMB + 1];
    const int k = blockIdx.x & (KC - 1);
    const bool raw = blockIdx.x >= KC;
    const int i = threadIdx.x;
    const float* A = cov + (size_t)k * EMB * EMB;
    for (int j = 0; j < EMB; j++) Ls[i][j] = A[i * EMB + j];
    if (!raw) Ls[i][i] += 0.005f;
    __syncthreads();
    for (int j = 0; j < EMB; j++) {
        if (i == j) {
            float s = Ls[j][j];
            for (int t = 0; t < j; t++) s -= Ls[j][t] * Ls[j][t];
            Ls[j][j] = sqrtf(s);
        }
        __syncthreads();
        if (i > j) {
            float s = Ls[i][j];
            for (int t = 0; t < j; t++) s -= Ls[i][t] * Ls[j][t];
            Ls[i][j] = s / Ls[j][j];
        }
        __syncthreads();
    }
    if (raw) {
        float* out = g_Lraw + (size_t)k * EMB * EMB;
        for (int j = 0; j < EMB; j++) out[i * EMB + j] = (j <= i) ? Ls[i][j] : 0.f;
    } else {
        if (i == 0) {
            float ld = 0.f;
            for (int t = 0; t < EMB; t++) ld += logf(Ls[t][t]);
            g_logdet[k] = 2.f * ld;
        }
        const int c = i;
        for (int r = 0; r < EMB; r++) {
            if (r < c) { Inv[r][c] = 0.f; continue; }
            float s = (r == c) ? 1.f : 0.f;
            for (int t = c; t < r; t++) s -= Ls[r][t] * Inv[t][c];
            Inv[r][c] = s / Ls[r][r];
        }
        __syncthreads();
        float* out = g_Linv + (size_t)k * EMB * EMB;
        for (int j = 0; j < EMB; j++) out[i * EMB + j] = Inv[i][j];
    }
}

// ---------------- identity detection ----------------
__global__ void ident_init_kernel() {
    if (threadIdx.x == 0 && blockIdx.x == 0) { g_ident = 1; g_identraw = 1; }
}
template<int RAW>
__global__ void ident_check_kernel() {
    const int k = blockIdx.x;
    const int i = threadIdx.x;
    const float* M = RAW ? g_Lraw : g_Linv;
    const float gamma = M[0];
    const float* L = M + (size_t)k * EMB * EMB + (size_t)i * EMB;
    bool ok = true;
    for (int j = 0; j < EMB; j++) {
        float v = L[j];
        if (j == i) { if (v != gamma) ok = false; }
        else        { if (v != 0.0f)  ok = false; }
    }
    if (!__syncthreads_and(ok ? 1 : 0)) {
        if (i == 0) atomicAnd(RAW ? &g_identraw : &g_ident, 0);
    }
}

// ---------------- identity fast-path lp (exact fp32) ----------------
__global__ void __launch_bounds__(128) ident_lp_kernel(
    const float* __restrict__ means, const float* __restrict__ sizes,
    float* __restrict__ lp)
{
    if (!g_ident) return;
    __shared__ float es[64][EMB];
    const int k = blockIdx.y * 128 + threadIdx.x;
    const int b0 = blockIdx.x * 64;
    const float gamma = g_Linv[0];
    const float g2 = gamma * gamma;

    float mu[EMB];
#pragma unroll
    for (int j = 0; j < EMB; j++) mu[j] = means[k * EMB + j];
    const float ck = logf(sizes[k]) - 0.5f * (64.f * LOG2PI_F + g_logdet[k]);

    for (int t = threadIdx.x; t < 64 * EMB / 4; t += 128) {
        int bb = t / (EMB / 4), jj = t % (EMB / 4);
        ((float4*)es[bb])[jj] = ((const float4*)(g_enc + (size_t)(b0 + bb) * EMB))[jj];
    }
    __syncthreads();

    for (int bb = 0; bb < 64; bb++) {
        float q = 0.f;
#pragma unroll
        for (int j = 0; j < EMB; j++) {
            float d = es[bb][j] - mu[j];
            q = fmaf(d, d, q);
        }
        lp[(size_t)(b0 + bb) * KC + k] = ck - 0.5f * g2 * q;
    }
}

// ---------------- Wp build (general path) ----------------
__global__ void __launch_bounds__(128) wp_build_kernel(
    const float* __restrict__ means, const float* __restrict__ sizes)
{
    if (g_ident) return;
    __shared__ float L[EMB * EMB];
    __shared__ float P[EMB * (EMB + 1)];
    __shared__ float pm[EMB];
    __shared__ float mu[EMB];
    __shared__ float ck;
    const int k = blockIdx.x;
    const int tid = threadIdx.x;

    for (int i = tid; i < (EMB * EMB) / 4; i += 128)
        ((float4*)L)[i] = ((const float4*)(g_Linv + (size_t)k * EMB * EMB))[i];
    if (tid < EMB) mu[tid] = means[k * EMB + tid];
    __syncthreads();

    for (int idx = tid; idx < EMB * EMB; idx += 128) {
        int i = idx >> 6, c = idx & 63;
        float s = 0.f;
        for (int d = 0; d < EMB; d++) s += L[d * EMB + i] * L[d * EMB + c];
        P[i * (EMB + 1) + c] = s;
    }
    __syncthreads();
    if (tid < EMB) {
        float s = 0.f;
        for (int j = 0; j < EMB; j++) s += P[tid * (EMB + 1) + j] * mu[j];
        pm[tid] = s;
    }
    __syncthreads();
    if (tid == 0) {
        float s = 0.f;
        for (int i = 0; i < EMB; i++) s += pm[i] * mu[i];
        ck = s + g_logdet[k] + 64.f * LOG2PI_F - 2.f * logf(sizes[k]);
    }
    __syncthreads();

    __nv_bfloat16* out = g_Wp + (size_t)k * K3Q;
    for (int t = tid; t < NFEAT; t += 128) {
        float w;
        if (t < NTRI) {
            int i, j; tri_ij(t, i, j);
            w = P[i * (EMB + 1) + j] * (i == j ? 1.f : 2.f);
        } else if (t < NTRI + EMB) {
            w = -2.f * pm[t - NTRI];
        } else if (t == NTRI + EMB) {
            w = ck;
        } else w = 0.f;
        __nv_bfloat16 h, l; split2(w, h, l);
        out[t] = h; out[NFEAT + t] = l; out[2 * NFEAT + t] = h;
    }
}

// ---------------- G build (general path) ----------------
__global__ void __launch_bounds__(256) g_build_kernel() {
    if (g_ident) return;
    __shared__ float e[EMB];
    const int b = blockIdx.x;
    const int tid = threadIdx.x;
    if (tid < EMB) e[tid] = g_enc[(size_t)b * EMB + tid];
    __syncthreads();
    __nv_bfloat16* out = g_Gs + (size_t)b * K3Q;
    for (int t = tid; t < NFEAT; t += 256) {
        float v;
        if (t < NTRI) {
            int i, j; tri_ij(t, i, j);
            v = e[i] * e[j];
        } else if (t < NTRI + EMB) {
            v = e[t - NTRI];
        } else if (t == NTRI + EMB) {
            v = 1.f;
        } else v = 0.f;
        __nv_bfloat16 h, l; split2(v, h, l);
        out[t] = h; out[NFEAT + t] = h; out[2 * NFEAT + t] = l;
    }
}

// ---------------- top-2 (writes idx directly when lp is exact) ----------------
__global__ void top2_kernel(const float* __restrict__ lp) {
    int row = (blockIdx.x * blockDim.x + threadIdx.x) >> 5;
    int lane = threadIdx.x & 31;
    if (row >= BATCH) return;
    const float* r = lp + (size_t)row * KC;

    float b1 = -INFINITY; int i1 = 0;
    for (int k = lane; k < KC; k += 32) {
        float v = r[k];
        if (v > b1 || (v == b1 && k < i1)) { b1 = v; i1 = k; }
    }
#pragma unroll
    for (int off = 16; off; off >>= 1) {
        float ov = __shfl_down_sync(0xffffffffu, b1, off);
        int   oi = __shfl_down_sync(0xffffffffu, i1, off);
        if (ov > b1 || (ov == b1 && oi < i1)) { b1 = ov; i1 = oi; }
    }
    b1 = __shfl_sync(0xffffffffu, b1, 0);
    i1 = __shfl_sync(0xffffffffu, i1, 0);

    if (g_ident) {
        if (lane == 0) g_idx[row] = i1;
        return;
    }

    float b2 = -INFINITY; int i2 = (i1 == 0) ? 1 : 0;
    for (int k = lane; k < KC; k += 32) {
        if (k == i1) continue;
        float v = r[k];
        if (v > b2 || (v == b2 && k < i2)) { b2 = v; i2 = k; }
    }
#pragma unroll
    for (int off = 16; off; off >>= 1) {
        float ov = __shfl_down_sync(0xffffffffu, b2, off);
        int   oi = __shfl_down_sync(0xffffffffu, i2, off);
        if (ov > b2 || (ov == b2 && oi < i2)) { b2 = ov; i2 = oi; }
    }
    if (lane == 0) { int2 t; t.x = i1; t.y = i2; g_top2[row] = t; }
}

// ---------------- exact fp32 refine (skipped when lp already exact) ----------------
__global__ void refine_kernel(const float* __restrict__ means, const float* __restrict__ sizes) {
    if (g_ident) return;
    int row = (blockIdx.x * blockDim.x + threadIdx.x) >> 5;
    int lane = threadIdx.x & 31;
    if (row >= BATCH) return;
    int2 cand = g_top2[row];

    float e0 = g_enc[(size_t)row * EMB + lane];
    float e1 = g_enc[(size_t)row * EMB + 32 + lane];

    float lp[2];
#pragma unroll
    for (int c = 0; c < 2; c++) {
        int k = c ? cand.y : cand.x;
        float d0 = e0 - means[k * EMB + lane];
        float d1 = e1 - means[k * EMB + 32 + lane];
        const float* L = g_Linv + (size_t)k * EMB * EMB;
        float s0 = 0.f, s1 = 0.f;
#pragma unroll 8
        for (int j = 0; j < 32; j++) {
            float dv = __shfl_sync(0xffffffffu, d0, j);
            s0 += L[lane * EMB + j] * dv;
            s1 += L[(lane + 32) * EMB + j] * dv;
        }
#pragma unroll 8
        for (int j = 0; j < 32; j++) {
            float dv = __shfl_sync(0xffffffffu, d1, j);
            s0 += L[lane * EMB + 32 + j] * dv;
            s1 += L[(lane + 32) * EMB + 32 + j] * dv;
        }
        float q = s0 * s0 + s1 * s1;
#pragma unroll
        for (int off = 16; off; off >>= 1) q += __shfl_down_sync(0xffffffffu, q, off);
        if (lane == 0)
            lp[c] = logf(sizes[k]) - 0.5f * (64.f * LOG2PI_F + g_logdet[k]) - 0.5f * q;
    }
    if (lane == 0) {
        int best = cand.x;
        if (lp[1] > lp[0] || (lp[1] == lp[0] && cand.y < cand.x)) best = cand.y;
        g_idx[row] = best;
    }
}

// ---------------- sample -> split-2 fp16 (identity fast path for Lraw) ----------------
__global__ void __launch_bounds__(64) sample_kernel(
    const float* __restrict__ noise, const float* __restrict__ means)
{
    const int b = blockIdx.x;
    const int t = threadIdx.x;
    const int k = g_idx[b];

    if (g_identraw) {
        const float gamma = g_Lraw[0];
        float s = means[k * EMB + t] + gamma * noise[(size_t)b * EMB + t];
        __half h, l; split2h(s, h, l);
        size_t base = (size_t)b * 2 * EMB;
        g_qs[base + t] = h; g_qs[base + EMB + t] = l;
        return;
    }

    __shared__ float sL[EMB * EMB];
    __shared__ float sn[EMB];
    const float* L = g_Lraw + (size_t)k * EMB * EMB;
    for (int i = t; i < (EMB * EMB) / 4; i += 64)
        ((float4*)sL)[i] = ((const float4*)L)[i];
    sn[t] = noise[(size_t)b * EMB + t];
    __syncthreads();
    float s = means[k * EMB + t];
    for (int j = 0; j <= t; j++) s += sL[t * EMB + j] * sn[j];
    __half h, l; split2h(s, h, l);
    size_t base = (size_t)b * 2 * EMB;
    g_qs[base + t] = h; g_qs[base + EMB + t] = l;
}

// ---------------- pack idx ----------------
__global__ void pack_kernel(float* __restrict__ out, int out_size) {
    int i = blockIdx.x * blockDim.x + threadIdx.x;
    if (out_size >= IDX_OFF + BATCH && i < BATCH)
        out[IDX_OFF + i] = (float)g_idx[i];
}

// ---------------- launch ----------------
extern "C" void kernel_launch(void* const* d_in, const int* in_sizes, int n_in,
                              void* d_out, int out_size)
{
    const float* x   = (const float*)d_in[0];
    const float* noi = (const float*)d_in[1];
    const float* eW1 = (const float*)d_in[2];
    const float* eb1 = (const float*)d_in[3];
    const float* eW2 = (const float*)d_in[4];
    const float* eb2 = (const float*)d_in[5];
    const float* eW3 = (const float*)d_in[6];
    const float* eb3 = (const float*)d_in[7];
    const float* dW1 = (const float*)d_in[8];
    const float* db1 = (const float*)d_in[9];
    const float* dW2 = (const float*)d_in[10];
    const float* db2 = (const float*)d_in[11];
    const float* dW3 = (const float*)d_in[12];
    const float* db3 = (const float*)d_in[13];
    const float* means = (const float*)d_in[14];
    const float* sizes = (const float*)d_in[15];
    const float* cov   = (const float*)d_in[16];
    float* out = (float*)d_out;

    __nv_bfloat16 *xs, *h1s, *h2s, *ew1s, *ew2s, *ew3s, *gs, *wp;
    __half *qs, *dw1s, *dw2s, *dw3s;
    float *enc;
    cudaGetSymbolAddress((void**)&xs,  g_xs);
    cudaGetSymbolAddress((void**)&h1s, g_h1s);
    cudaGetSymbolAddress((void**)&h2s, g_h2s);
    cudaGetSymbolAddress((void**)&qs,  g_qs);
    cudaGetSymbolAddress((void**)&ew1s, g_eW1s);
    cudaGetSymbolAddress((void**)&ew2s, g_eW2s);
    cudaGetSymbolAddress((void**)&ew3s, g_eW3s);
    cudaGetSymbolAddress((void**)&dw1s, g_dW1s);
    cudaGetSymbolAddress((void**)&dw2s, g_dW2s);
    cudaGetSymbolAddress((void**)&dw3s, g_dW3s);
    cudaGetSymbolAddress((void**)&gs,  g_Gs);
    cudaGetSymbolAddress((void**)&wp,  g_Wp);
    cudaGetSymbolAddress((void**)&enc, g_enc);

    const int SM128 = 3 * ((128 + 128) * 128);   // 98304
    const int SM64  = 3 * ((64 + 64) * 128);     // 49152
    cudaFuncSetAttribute(mma_gemm<128, 128, 3, 1, 0>, cudaFuncAttributeMaxDynamicSharedMemorySize, SM128);
    cudaFuncSetAttribute(mma_gemm<128, 128, 3, 2, 0>, cudaFuncAttributeMaxDynamicSharedMemorySize, SM128);
    cudaFuncSetAttribute(mma_gemm<64, 64, 3, 0, 0>,   cudaFuncAttributeMaxDynamicSharedMemorySize, SM64);
    cudaFuncSetAttribute(mma_gemm<128, 128, 3, 4, 1>, cudaFuncAttributeMaxDynamicSharedMemorySize, SM128);
    cudaFuncSetAttribute(mma_gemm<128, 128, 3, 0, 1>, cudaFuncAttributeMaxDynamicSharedMemorySize, SM128);

    // ---- encoder (bf16 split-3, exact-grade) ----
    split_a_kernel<<<(BATCH * IN_DIM / 4 + 255) / 256, 256>>>(x, xs, BATCH * IN_DIM, IN_DIM);
    split_w_kernel<<<(DENSE * IN_DIM / 4 + 255) / 256, 256>>>(eW1, ew1s, DENSE * IN_DIM, IN_DIM);
    split_w_kernel<<<(DENSE * DENSE / 4 + 255) / 256, 256>>>(eW2, ew2s, DENSE * DENSE, DENSE);
    mma_gemm<128, 128, 3, 1, 0><<<dim3(DENSE / 128, BATCH / 128), 256, SM128>>>(
        xs, ew1s, eb1, h1s, DENSE, 3 * IN_DIM);
    chol_kernel<<<2 * KC, EMB>>>(cov);
    mma_gemm<128, 128, 3, 1, 0><<<dim3(DENSE / 128, BATCH / 128), 256, SM128>>>(
        h1s, ew2s, eb2, h2s, DENSE, 3 * DENSE);
    ident_init_kernel<<<1, 32>>>();
    ident_check_kernel<0><<<KC, EMB>>>();
    ident_check_kernel<1><<<KC, EMB>>>();
    wp_build_kernel<<<KC, 128>>>(means, sizes);
    split_w_kernel<<<(EMB * DENSE / 4 + 255) / 256, 256>>>(eW3, ew3s, EMB * DENSE, DENSE);
    mma_gemm<64, 64, 3, 0, 0><<<dim3(EMB / 64, BATCH / 64), 256, SM64>>>(
        h2s, ew3s, eb3, enc, EMB, 3 * DENSE);

    // ---- GMM log-probs: identity fast path OR tri-feature GEMM ----
    g_build_kernel<<<BATCH, 256>>>();
    mma_gemm<128, 128, 3, 2, 0><<<dim3(KC / 128, BATCH / 128), 256, SM128>>>(
        gs, wp, nullptr, out + LP_OFF, KC, K3Q);
    ident_lp_kernel<<<dim3(BATCH / 64, KC / 128), 128>>>(means, sizes, out + LP_OFF);
    top2_kernel<<<(BATCH * 32) / 256, 256>>>(out + LP_OFF);
    refine_kernel<<<(BATCH * 32) / 256, 256>>>(means, sizes);
    sample_kernel<<<BATCH, EMB>>>(noi, means);

    // ---- decoder: d1 fp16 2-term, d2/d3 fp16 1-term ----
    split_wh_kernel<<<(DENSE * EMB / 4 + 255) / 256, 256>>>(dW1, dw1s, DENSE * EMB, EMB);
    cvt_h_kernel<<<(DENSE * DENSE / 4 + 255) / 256, 256>>>(dW2, dw2s, DENSE * DENSE);
    cvt_h_kernel<<<(IN_DIM * DENSE / 4 + 255) / 256, 256>>>(dW3, dw3s, IN_DIM * DENSE);
    mma_gemm<128, 128, 3, 4, 1><<<dim3(DENSE / 128, BATCH / 128), 256, SM128>>>(   // d1: K=128 (2-term)
        qs, dw1s, db1, h1s, DENSE, 2 * EMB);
    mma_gemm<128, 128, 3, 4, 1><<<dim3(DENSE / 128, BATCH / 128), 256, SM128>>>(   // d2: K=1152 (1-term)
        h1s, dw2s, db2, h2s, DENSE, DENSE);
    mma_gemm<128, 128, 3, 0, 1><<<dim3(IN_DIM / 128, BATCH / 128), 256, SM128>>>(  // d3: K=1152 (1-term)
        h2s, dw3s, db3, out, IN_DIM, DENSE);

    pack_kernel<<<(BATCH + 255) / 256, 256>>>(out, out_size);
}

// round 17
// speedup vs baseline: 1.6225x; 1.0157x over previous
#include <cuda_runtime.h>
#include <cuda_bf16.h>
#include <cuda_fp16.h>
#include <math.h>
#include <stdint.h>

#define BATCH   8192
#define IN_DIM  512
#define EMB     64
#define KC      256
#define DENSE   1152
#define NTRI    2080
#define NFEAT   2176
#define K3Q     (3*NFEAT)
#define LP_OFF  (BATCH*IN_DIM)
#define IDX_OFF (LP_OFF + BATCH*KC)
#define LOG2PI_F 1.8378770664093453f

// ---------------- scratch ----------------
__device__ __align__(128) __nv_bfloat16 g_xs  [BATCH * 3 * IN_DIM];
__device__ __align__(128) __nv_bfloat16 g_h1s [BATCH * 3 * DENSE];
__device__ __align__(128) __nv_bfloat16 g_h2s [BATCH * 3 * DENSE];
__device__ __align__(128) __half        g_qs  [BATCH * 2 * EMB];
__device__ __align__(128) __nv_bfloat16 g_eW1s[DENSE * 3 * IN_DIM];
__device__ __align__(128) __nv_bfloat16 g_eW2s[DENSE * 3 * DENSE];
__device__ __align__(128) __nv_bfloat16 g_eW3s[EMB   * 3 * DENSE];
__device__ __align__(128) __half        g_dW1s[DENSE * 2 * EMB];
__device__ __align__(128) __half        g_dW2s[DENSE * DENSE];
__device__ __align__(128) __half        g_dW3s[IN_DIM * DENSE];
__device__ __align__(128) __nv_bfloat16 g_Gs  [(size_t)BATCH * K3Q];
__device__ __align__(128) __nv_bfloat16 g_Wp  [(size_t)KC * K3Q];
__device__ float g_enc [BATCH * EMB];
__device__ float g_Linv[KC * EMB * EMB];
__device__ float g_Lraw[KC * EMB * EMB];
__device__ float g_logdet[KC];
__device__ int   g_ident;
__device__ int   g_identraw;

// ---------------- helpers ----------------
__device__ __forceinline__ float selu_f(float x) {
    const float scale = 1.0507009873554805f;
    const float alpha = 1.6732632423543772f;
    return scale * (x > 0.f ? x : alpha * expm1f(x));
}
__device__ __forceinline__ void split2(float v, __nv_bfloat16& hi, __nv_bfloat16& lo) {
    hi = __float2bfloat16(v);
    lo = __float2bfloat16(v - __bfloat162float(hi));
}
__device__ __forceinline__ void split2h(float v, __half& hi, __half& lo) {
    hi = __float2half_rn(v);
    lo = __float2half_rn(v - __half2float(hi));
}
__device__ __forceinline__ uint32_t pack_bf2(__nv_bfloat16 a, __nv_bfloat16 b) {
    __nv_bfloat162 t; t.x = a; t.y = b;
    return *reinterpret_cast<uint32_t*>(&t);
}
__device__ __forceinline__ uint32_t pack_h2(__half a, __half b) {
    __half2 t; t.x = a; t.y = b;
    return *reinterpret_cast<uint32_t*>(&t);
}
__device__ __forceinline__ uint32_t smem_u32(const void* p) {
    uint32_t a;
    asm("{ .reg .u64 t; cvta.to.shared.u64 t, %1; cvt.u32.u64 %0, t; }" : "=r"(a) : "l"(p));
    return a;
}
__device__ __forceinline__ void cp16(uint32_t dst, const void* src) {
    asm volatile("cp.async.cg.shared.global [%0], [%1], 16;" :: "r"(dst), "l"(src));
}
__device__ __forceinline__ uint32_t sw128(uint32_t off) { return off ^ ((off >> 3) & 0x70); }

__device__ __forceinline__ void ldsm4(uint32_t& r0, uint32_t& r1, uint32_t& r2, uint32_t& r3,
                                      uint32_t addr) {
    asm volatile("ldmatrix.sync.aligned.m8n8.x4.shared.b16 {%0,%1,%2,%3}, [%4];"
        : "=r"(r0), "=r"(r1), "=r"(r2), "=r"(r3) : "r"(addr));
}
__device__ __forceinline__ void mma_bf16(float* c,
    uint32_t a0, uint32_t a1, uint32_t a2, uint32_t a3, uint32_t b0, uint32_t b1) {
    asm volatile("mma.sync.aligned.m16n8k16.row.col.f32.bf16.bf16.f32 "
        "{%0,%1,%2,%3}, {%4,%5,%6,%7}, {%8,%9}, {%0,%1,%2,%3};"
        : "+f"(c[0]), "+f"(c[1]), "+f"(c[2]), "+f"(c[3])
        : "r"(a0), "r"(a1), "r"(a2), "r"(a3), "r"(b0), "r"(b1));
}
__device__ __forceinline__ void mma_f16(float* c,
    uint32_t a0, uint32_t a1, uint32_t a2, uint32_t a3, uint32_t b0, uint32_t b1) {
    asm volatile("mma.sync.aligned.m16n8k16.row.col.f32.f16.f16.f32 "
        "{%0,%1,%2,%3}, {%4,%5,%6,%7}, {%8,%9}, {%0,%1,%2,%3};"
        : "+f"(c[0]), "+f"(c[1]), "+f"(c[2]), "+f"(c[3])
        : "r"(a0), "r"(a1), "r"(a2), "r"(a3), "r"(b0), "r"(b1));
}
__device__ __forceinline__ void tri_ij(int t, int& i, int& j) {
    int ii = (int)((sqrtf(8.f * (float)t + 1.f) - 1.f) * 0.5f);
    if ((ii + 1) * (ii + 2) / 2 <= t) ii++;
    if (ii * (ii + 1) / 2 > t) ii--;
    i = ii; j = t - ii * (ii + 1) / 2;
}

// ---------------- split primitives (device) ----------------
__device__ __forceinline__ void do_split3(const float* __restrict__ in,
                                          __nv_bfloat16* __restrict__ out,
                                          int i4, int K, bool amode) {
    int r = i4 / K, c = i4 % K;
    float4 v = *(const float4*)(in + i4);
    __nv_bfloat16 h0, l0, h1, l1, h2, l2, h3, l3;
    split2(v.x, h0, l0); split2(v.y, h1, l1); split2(v.z, h2, l2); split2(v.w, h3, l3);
    uint32_t hA = pack_bf2(h0, h1), hB = pack_bf2(h2, h3);
    uint32_t lA = pack_bf2(l0, l1), lB = pack_bf2(l2, l3);
    size_t b = (size_t)r * 3 * K + c;
    if (amode) {   // [hi | hi | lo]
        *(uint32_t*)(out + b)         = hA; *(uint32_t*)(out + b + 2)         = hB;
        *(uint32_t*)(out + b + K)     = hA; *(uint32_t*)(out + b + K + 2)     = hB;
        *(uint32_t*)(out + b + 2 * K) = lA; *(uint32_t*)(out + b + 2 * K + 2) = lB;
    } else {       // [hi | lo | hi]
        *(uint32_t*)(out + b)         = hA; *(uint32_t*)(out + b + 2)         = hB;
        *(uint32_t*)(out + b + K)     = lA; *(uint32_t*)(out + b + K + 2)     = lB;
        *(uint32_t*)(out + b + 2 * K) = hA; *(uint32_t*)(out + b + 2 * K + 2) = hB;
    }
}

// ---------------- merged encoder converts ----------------
// blocks: x [0,4096) | eW1 [4096,4672) | eW2 [4672,5968) | eW3 [5968,6040)
#define CE_NB (4096 + 576 + 1296 + 72)
__global__ void __launch_bounds__(256) conv_enc_kernel(
    const float* __restrict__ x,  const float* __restrict__ eW1,
    const float* __restrict__ eW2, const float* __restrict__ eW3,
    __nv_bfloat16* __restrict__ xs,  __nv_bfloat16* __restrict__ ew1s,
    __nv_bfloat16* __restrict__ ew2s, __nv_bfloat16* __restrict__ ew3s)
{
    int b = blockIdx.x;
    if (b < 4096) {
        int i4 = (b * 256 + threadIdx.x) * 4;
        if (i4 < BATCH * IN_DIM) do_split3(x, xs, i4, IN_DIM, true);
    } else if (b < 4672) {
        int i4 = ((b - 4096) * 256 + threadIdx.x) * 4;
        if (i4 < DENSE * IN_DIM) do_split3(eW1, ew1s, i4, IN_DIM, false);
    } else if (b < 5968) {
        int i4 = ((b - 4672) * 256 + threadIdx.x) * 4;
        if (i4 < DENSE * DENSE) do_split3(eW2, ew2s, i4, DENSE, false);
    } else {
        int i4 = ((b - 5968) * 256 + threadIdx.x) * 4;
        if (i4 < EMB * DENSE) do_split3(eW3, ew3s, i4, DENSE, false);
    }
}

// ---------------- merged decoder converts ----------------
// blocks: dW1 [0,72) split-2plane | dW2 [72,1368) 1-plane | dW3 [1368,1944) 1-plane
#define CD_NB (72 + 1296 + 576)
__global__ void __launch_bounds__(256) conv_dec_kernel(
    const float* __restrict__ dW1, const float* __restrict__ dW2, const float* __restrict__ dW3,
    __half* __restrict__ dw1s, __half* __restrict__ dw2s, __half* __restrict__ dw3s)
{
    int b = blockIdx.x;
    if (b < 72) {
        int i4 = (b * 256 + threadIdx.x) * 4;
        if (i4 < DENSE * EMB) {
            int r = i4 / EMB, c = i4 % EMB;
            float4 v = *(const float4*)(dW1 + i4);
            uint32_t hA = pack_h2(__float2half_rn(v.x), __float2half_rn(v.y));
            uint32_t hB = pack_h2(__float2half_rn(v.z), __float2half_rn(v.w));
            size_t o = (size_t)r * 2 * EMB + c;
            *(uint32_t*)(dw1s + o)       = hA; *(uint32_t*)(dw1s + o + 2)       = hB;
            *(uint32_t*)(dw1s + o + EMB) = hA; *(uint32_t*)(dw1s + o + EMB + 2) = hB;
        }
    } else if (b < 1368) {
        int i4 = ((b - 72) * 256 + threadIdx.x) * 4;
        if (i4 < DENSE * DENSE) {
            float4 v = *(const float4*)(dW2 + i4);
            *(uint32_t*)(dw2s + i4)     = pack_h2(__float2half_rn(v.x), __float2half_rn(v.y));
            *(uint32_t*)(dw2s + i4 + 2) = pack_h2(__float2half_rn(v.z), __float2half_rn(v.w));
        }
    } else {
        int i4 = ((b - 1368) * 256 + threadIdx.x) * 4;
        if (i4 < IN_DIM * DENSE) {
            float4 v = *(const float4*)(dW3 + i4);
            *(uint32_t*)(dw3s + i4)     = pack_h2(__float2half_rn(v.x), __float2half_rn(v.y));
            *(uint32_t*)(dw3s + i4 + 2) = pack_h2(__float2half_rn(v.z), __float2half_rn(v.w));
        }
    }
}

// ================= tensor-core GEMM via mma.sync =================
// MODE 0: fp32 +bias. MODE 1: SELU + bf16 3-plane. MODE 2: -0.5*acc lp (skip if ident).
// MODE 4: SELU + fp16 1-plane.
template<int BM, int BN, int STAGES, int MODE, int FP16>
__global__ void __launch_bounds__(256) mma_gemm(
    const void* __restrict__ Ain, const void* __restrict__ Win,
    const float* __restrict__ bias, void* __restrict__ Cout,
    int N, int KX)
{
    if (MODE == 2 && g_ident) return;

    constexpr int ABYTES = BM * 128;
    constexpr int BBYTES = BN * 128;
    constexpr int BUF = ABYTES + BBYTES;
    constexpr int NF = BN / 16;
    constexpr int WR = BM / 4;
    constexpr int MI = (WR >= 16) ? (WR / 16) : 1;

    const uint16_t* A = (const uint16_t*)Ain;
    const uint16_t* W = (const uint16_t*)Win;

    extern __shared__ __align__(1024) char smem[];
    const uint32_t sbase = smem_u32(smem);

    const int tid = threadIdx.x;
    const int lane = tid & 31;
    const int wid = tid >> 5;
    const int wm = wid & 3;
    const int wn = wid >> 2;
    const int bm = blockIdx.y * BM;
    const int bn = blockIdx.x * BN;

    float acc[MI][NF][4];
#pragma unroll
    for (int i = 0; i < MI; i++)
#pragma unroll
        for (int j = 0; j < NF; j++)
#pragma unroll
            for (int c = 0; c < 4; c++) acc[i][j][c] = 0.f;

    const int nk = KX >> 6;

    auto load_tile = [&](int ck, int b) {
        const uint32_t aB = sbase + (uint32_t)b * BUF;
        const uint32_t bB = aB + ABYTES;
        const uint16_t* Ap = A + (size_t)bm * KX + ck * 64;
        const uint16_t* Wq = W + (size_t)bn * KX + ck * 64;
#pragma unroll
        for (int t = 0; t < (BM * 8) / 256; t++) {
            int idx = tid + t * 256;
            int r = idx >> 3, c = idx & 7;
            cp16(aB + sw128((uint32_t)(r * 128 + c * 16)), Ap + (size_t)r * KX + c * 8);
        }
#pragma unroll
        for (int t = 0; t < (BN * 8) / 256; t++) {
            int idx = tid + t * 256;
            int r = idx >> 3, c = idx & 7;
            cp16(bB + sw128((uint32_t)(r * 128 + c * 16)), Wq + (size_t)r * KX + c * 8);
        }
        asm volatile("cp.async.commit_group;" ::: "memory");
    };

    const int ar = wm * WR + (lane & 15);
    const int br = wn * (BN / 2) + (lane & 15);
    const uint32_t kh = (uint32_t)((lane >> 4) * 16);

    uint32_t arsw[MI], brsw[NF / 2];
#pragma unroll
    for (int mi = 0; mi < MI; mi++) arsw[mi] = sw128((uint32_t)((ar + 16 * mi) * 128));
#pragma unroll
    for (int p = 0; p < NF / 2; p++) brsw[p] = sw128((uint32_t)((br + 16 * p) * 128));

    if (STAGES == 3) { load_tile(0, 0); if (nk > 1) load_tile(1, 1); }
    else             { load_tile(0, 0); }

    int buf = 0;
    for (int ck = 0; ck < nk; ck++) {
        if (STAGES == 2) {
            if (ck + 1 < nk) load_tile(ck + 1, buf ^ 1);
            if (ck + 1 < nk) asm volatile("cp.async.wait_group 1;" ::: "memory");
            else             asm volatile("cp.async.wait_group 0;" ::: "memory");
            __syncthreads();
        } else {
            if (ck < nk - 1) asm volatile("cp.async.wait_group 1;" ::: "memory");
            else             asm volatile("cp.async.wait_group 0;" ::: "memory");
            __syncthreads();
            if (ck + 2 < nk) {
                int nb = buf + 2; if (nb >= 3) nb -= 3;
                load_tile(ck + 2, nb);
            }
        }

        const uint32_t aB = sbase + (uint32_t)buf * BUF;
        const uint32_t bB = aB + ABYTES;
#pragma unroll
        for (int ks = 0; ks < 4; ks++) {
            const uint32_t kcol = (uint32_t)(ks * 32) + kh;
            uint32_t a[MI][4];
#pragma unroll
            for (int mi = 0; mi < MI; mi++)
                ldsm4(a[mi][0], a[mi][1], a[mi][2], a[mi][3], aB + (arsw[mi] ^ kcol));
            uint32_t bf[NF][2];
#pragma unroll
            for (int p = 0; p < NF / 2; p++) {
                uint32_t r0, r1, r2, r3;
                ldsm4(r0, r1, r2, r3, bB + (brsw[p] ^ kcol));
                bf[2 * p][0] = r0; bf[2 * p][1] = r2;
                bf[2 * p + 1][0] = r1; bf[2 * p + 1][1] = r3;
            }
#pragma unroll
            for (int mi = 0; mi < MI; mi++)
#pragma unroll
                for (int nf = 0; nf < NF; nf++) {
                    if (FP16) mma_f16(acc[mi][nf], a[mi][0], a[mi][1], a[mi][2], a[mi][3],
                                      bf[nf][0], bf[nf][1]);
                    else      mma_bf16(acc[mi][nf], a[mi][0], a[mi][1], a[mi][2], a[mi][3],
                                       bf[nf][0], bf[nf][1]);
                }
        }
        if (STAGES == 2) __syncthreads();
        buf++; if (buf == STAGES) buf = 0;
    }

    const int row0 = bm + wm * WR + (lane >> 2);
    const int colb = bn + wn * (BN / 2) + (lane & 3) * 2;
#pragma unroll
    for (int mi = 0; mi < MI; mi++) {
#pragma unroll
        for (int nf = 0; nf < NF; nf++) {
            const int col = colb + nf * 8;
            float b0 = 0.f, b1 = 0.f;
            if (MODE != 2) { b0 = bias[col]; b1 = bias[col + 1]; }
#pragma unroll
            for (int h = 0; h < 2; h++) {
                const int m = row0 + mi * 16 + h * 8;
                float v0 = acc[mi][nf][2 * h + 0] + b0;
                float v1 = acc[mi][nf][2 * h + 1] + b1;
                if (MODE == 0) {
                    float2 o; o.x = v0; o.y = v1;
                    *(float2*)((float*)Cout + (size_t)m * N + col) = o;
                } else if (MODE == 2) {
                    float2 o; o.x = -0.5f * v0; o.y = -0.5f * v1;
                    *(float2*)((float*)Cout + (size_t)m * N + col) = o;
                } else if (MODE == 4) {
                    v0 = selu_f(v0); v1 = selu_f(v1);
                    __half* C = (__half*)Cout;
                    *(uint32_t*)(C + (size_t)m * N + col) =
                        pack_h2(__float2half_rn(v0), __float2half_rn(v1));
                } else if (FP16) {
                    v0 = selu_f(v0); v1 = selu_f(v1);
                    __half h0, l0, h1, l1;
                    split2h(v0, h0, l0); split2h(v1, h1, l1);
                    __half* C = (__half*)Cout;
                    const size_t base = (size_t)m * (2 * (size_t)N) + col;
                    *(uint32_t*)(C + base)     = pack_h2(h0, h1);
                    *(uint32_t*)(C + base + N) = pack_h2(l0, l1);
                } else {
                    v0 = selu_f(v0); v1 = selu_f(v1);
                    __nv_bfloat16 h0, l0, h1, l1;
                    split2(v0, h0, l0); split2(v1, h1, l1);
                    uint32_t hh = pack_bf2(h0, h1);
                    uint32_t ll = pack_bf2(l0, l1);
                    __nv_bfloat16* C = (__nv_bfloat16*)Cout;
                    const size_t base = (size_t)m * (3 * (size_t)N) + col;
                    *(uint32_t*)(C + base)         = hh;
                    *(uint32_t*)(C + base + N)     = hh;
                    *(uint32_t*)(C + base + 2 * N) = ll;
                }
            }
        }
    }
}

// ---------------- Cholesky (+ inverse & logdet, + flag init) ----------------
__global__ void chol_kernel(const float* __restrict__ cov) {
    __shared__ float Ls[EMB][EMB + 1];
    __shared__ float Inv[EMB][EMB + 1];
    const int k = blockIdx.x & (KC - 1);
    const bool raw = blockIdx.x >= KC;
    const int i = threadIdx.x;
    if (blockIdx.x == 0 && i == 0) { g_ident = 1; g_identraw = 1; }   // read only by later kernels
    const float* A = cov + (size_t)k * EMB * EMB;
    for (int j = 0; j < EMB; j++) Ls[i][j] = A[i * EMB + j];
    if (!raw) Ls[i][i] += 0.005f;
    __syncthreads();
    for (int j = 0; j < EMB; j++) {
        if (i == j) {
            float s = Ls[j][j];
            for (int t = 0; t < j; t++) s -= Ls[j][t] * Ls[j][t];
            Ls[j][j] = sqrtf(s);
        }
        __syncthreads();
        if (i > j) {
            float s = Ls[i][j];
            for (int t = 0; t < j; t++) s -= Ls[i][t] * Ls[j][t];
            Ls[i][j] = s / Ls[j][j];
        }
        __syncthreads();
    }
    if (raw) {
        float* out = g_Lraw + (size_t)k * EMB * EMB;
        for (int j = 0; j < EMB; j++) out[i * EMB + j] = (j <= i) ? Ls[i][j] : 0.f;
    } else {
        if (i == 0) {
            float ld = 0.f;
            for (int t = 0; t < EMB; t++) ld += logf(Ls[t][t]);
            g_logdet[k] = 2.f * ld;
        }
        const int c = i;
        for (int r = 0; r < EMB; r++) {
            if (r < c) { Inv[r][c] = 0.f; continue; }
            float s = (r == c) ? 1.f : 0.f;
            for (int t = c; t < r; t++) s -= Ls[r][t] * Inv[t][c];
            Inv[r][c] = s / Ls[r][r];
        }
        __syncthreads();
        float* out = g_Linv + (size_t)k * EMB * EMB;
        for (int j = 0; j < EMB; j++) out[i * EMB + j] = Inv[i][j];
    }
}

// ---------------- merged identity detection (grid 2*KC) ----------------
__global__ void ident_check_kernel() {
    const int k = blockIdx.x & (KC - 1);
    const bool raw = blockIdx.x >= KC;
    const int i = threadIdx.x;
    const float* M = raw ? g_Lraw : g_Linv;
    const float gamma = M[0];
    const float* L = M + (size_t)k * EMB * EMB + (size_t)i * EMB;
    bool ok = true;
    for (int j = 0; j < EMB; j++) {
        float v = L[j];
        if (j == i) { if (v != gamma) ok = false; }
        else        { if (v != 0.0f)  ok = false; }
    }
    if (!__syncthreads_and(ok ? 1 : 0)) {
        if (i == 0) atomicAnd(raw ? &g_identraw : &g_ident, 0);
    }
}

// ---------------- identity fast-path lp (exact fp32) ----------------
__global__ void __launch_bounds__(128) ident_lp_kernel(
    const float* __restrict__ means, const float* __restrict__ sizes,
    float* __restrict__ lp)
{
    if (!g_ident) return;
    __shared__ float es[64][EMB];
    const int k = blockIdx.y * 128 + threadIdx.x;
    const int b0 = blockIdx.x * 64;
    const float gamma = g_Linv[0];
    const float g2 = gamma * gamma;

    float mu[EMB];
#pragma unroll
    for (int j = 0; j < EMB; j++) mu[j] = means[k * EMB + j];
    const float ck = logf(sizes[k]) - 0.5f * (64.f * LOG2PI_F + g_logdet[k]);

    for (int t = threadIdx.x; t < 64 * EMB / 4; t += 128) {
        int bb = t / (EMB / 4), jj = t % (EMB / 4);
        ((float4*)es[bb])[jj] = ((const float4*)(g_enc + (size_t)(b0 + bb) * EMB))[jj];
    }
    __syncthreads();

    for (int bb = 0; bb < 64; bb++) {
        float q = 0.f;
#pragma unroll
        for (int j = 0; j < EMB; j++) {
            float d = es[bb][j] - mu[j];
            q = fmaf(d, d, q);
        }
        lp[(size_t)(b0 + bb) * KC + k] = ck - 0.5f * g2 * q;
    }
}

// ---------------- merged wp_build + g_build (general path; no-ops when ident) ----------------
__global__ void __launch_bounds__(256) wpg_build_kernel(
    const float* __restrict__ means, const float* __restrict__ sizes)
{
    if (g_ident) return;
    const int tid = threadIdx.x;
    if (blockIdx.x < KC) {
        // ---- wp_build for cluster k ----
        __shared__ float L[EMB * EMB];
        __shared__ float P[EMB * (EMB + 1)];
        __shared__ float pm[EMB];
        __shared__ float mu[EMB];
        __shared__ float ck;
        const int k = blockIdx.x;
        for (int i = tid; i < (EMB * EMB) / 4; i += 256)
            ((float4*)L)[i] = ((const float4*)(g_Linv + (size_t)k * EMB * EMB))[i];
        if (tid < EMB) mu[tid] = means[k * EMB + tid];
        __syncthreads();
        for (int idx = tid; idx < EMB * EMB; idx += 256) {
            int i = idx >> 6, c = idx & 63;
            float s = 0.f;
            for (int d = 0; d < EMB; d++) s += L[d * EMB + i] * L[d * EMB + c];
            P[i * (EMB + 1) + c] = s;
        }
        __syncthreads();
        if (tid < EMB) {
            float s = 0.f;
            for (int j = 0; j < EMB; j++) s += P[tid * (EMB + 1) + j] * mu[j];
            pm[tid] = s;
        }
        __syncthreads();
        if (tid == 0) {
            float s = 0.f;
            for (int i = 0; i < EMB; i++) s += pm[i] * mu[i];
            ck = s + g_logdet[k] + 64.f * LOG2PI_F - 2.f * logf(sizes[k]);
        }
        __syncthreads();
        __nv_bfloat16* out = g_Wp + (size_t)k * K3Q;
        for (int t = tid; t < NFEAT; t += 256) {
            float w;
            if (t < NTRI) {
                int i, j; tri_ij(t, i, j);
                w = P[i * (EMB + 1) + j] * (i == j ? 1.f : 2.f);
            } else if (t < NTRI + EMB) {
                w = -2.f * pm[t - NTRI];
            } else if (t == NTRI + EMB) {
                w = ck;
            } else w = 0.f;
            __nv_bfloat16 h, l; split2(w, h, l);
            out[t] = h; out[NFEAT + t] = l; out[2 * NFEAT + t] = h;   // [hi|lo|hi]
        }
    } else {
        // ---- g_build for batch row b ----
        __shared__ float e[EMB];
        const int b = blockIdx.x - KC;
        if (tid < EMB) e[tid] = g_enc[(size_t)b * EMB + tid];
        __syncthreads();
        __nv_bfloat16* out = g_Gs + (size_t)b * K3Q;
        for (int t = tid; t < NFEAT; t += 256) {
            float v;
            if (t < NTRI) {
                int i, j; tri_ij(t, i, j);
                v = e[i] * e[j];
            } else if (t < NTRI + EMB) {
                v = e[t - NTRI];
            } else if (t == NTRI + EMB) {
                v = 1.f;
            } else v = 0.f;
            __nv_bfloat16 h, l; split2(v, h, l);
            out[t] = h; out[NFEAT + t] = h; out[2 * NFEAT + t] = l;   // [hi|hi|lo]
        }
    }
}

// ---------------- fused argmax + refine + sample + idx-out (one block per row) ----------------
__global__ void __launch_bounds__(64) argmax_sample_kernel(
    const float* __restrict__ lp, const float* __restrict__ noise,
    const float* __restrict__ means, const float* __restrict__ sizes,
    float* __restrict__ out, int out_size)
{
    __shared__ float sv[64];
    __shared__ int   si[64];
    __shared__ float slp[2];
    __shared__ int   scand[2];
    __shared__ int   skstar;

    const int b = blockIdx.x;
    const int t = threadIdx.x;
    const float* r = lp + (size_t)b * KC;

    // ---- top-1 (min-index tie-break) ----
    float b1 = -INFINITY; int i1 = 0;
    for (int k = t; k < KC; k += 64) {
        float v = r[k];
        if (v > b1 || (v == b1 && k < i1)) { b1 = v; i1 = k; }
    }
    sv[t] = b1; si[t] = i1;
    __syncthreads();
    for (int s = 32; s > 0; s >>= 1) {
        if (t < s) {
            float ov = sv[t + s]; int oi = si[t + s];
            if (ov > sv[t] || (ov == sv[t] && oi < si[t])) { sv[t] = ov; si[t] = oi; }
        }
        __syncthreads();
    }
    i1 = si[0];
    __syncthreads();

    int kstar;
    if (g_ident) {
        kstar = i1;          // lp exact -> exact argmax
    } else {
        // ---- top-2 ----
        float b2 = -INFINITY; int i2 = 0;
        for (int k = t; k < KC; k += 64) {
            if (k == i1) continue;
            float v = r[k];
            if (v > b2 || (v == b2 && k < i2)) { b2 = v; i2 = k; }
        }
        sv[t] = b2; si[t] = i2;
        __syncthreads();
        for (int s = 32; s > 0; s >>= 1) {
            if (t < s) {
                float ov = sv[t + s]; int oi = si[t + s];
                if (ov > sv[t] || (ov == sv[t] && oi < si[t])) { sv[t] = ov; si[t] = oi; }
            }
            __syncthreads();
        }
        const int i2f = si[0];
        __syncthreads();

        // ---- exact fp32 refine: warp w handles candidate w ----
        const int w = t >> 5;
        const int lane = t & 31;
        const int kc = (w == 0) ? i1 : i2f;
        float e0 = g_enc[(size_t)b * EMB + lane];
        float e1 = g_enc[(size_t)b * EMB + 32 + lane];
        float d0 = e0 - means[kc * EMB + lane];
        float d1 = e1 - means[kc * EMB + 32 + lane];
        const float* L = g_Linv + (size_t)kc * EMB * EMB;
        float s0 = 0.f, s1 = 0.f;
#pragma unroll 8
        for (int j = 0; j < 32; j++) {
            float dv = __shfl_sync(0xffffffffu, d0, j);
            s0 += L[lane * EMB + j] * dv;
            s1 += L[(lane + 32) * EMB + j] * dv;
        }
#pragma unroll 8
        for (int j = 0; j < 32; j++) {
            float dv = __shfl_sync(0xffffffffu, d1, j);
            s0 += L[lane * EMB + 32 + j] * dv;
            s1 += L[(lane + 32) * EMB + 32 + j] * dv;
        }
        float q = s0 * s0 + s1 * s1;
#pragma unroll
        for (int off = 16; off; off >>= 1) q += __shfl_down_sync(0xffffffffu, q, off);
        if (lane == 0) {
            slp[w] = logf(sizes[kc]) - 0.5f * (64.f * LOG2PI_F + g_logdet[kc]) - 0.5f * q;
            scand[w] = kc;
        }
        __syncthreads();
        if (t == 0) {
            int best = scand[0];
            if (slp[1] > slp[0] || (slp[1] == slp[0] && scand[1] < scand[0])) best = scand[1];
            skstar = best;
        }
        __syncthreads();
        kstar = skstar;
    }

    // ---- sample -> split-2 fp16 ----
    if (g_identraw) {
        const float gamma = g_Lraw[0];
        float s = means[kstar * EMB + t] + gamma * noise[(size_t)b * EMB + t];
        __half h, l; split2h(s, h, l);
        size_t base = (size_t)b * 2 * EMB;
        g_qs[base + t] = h; g_qs[base + EMB + t] = l;
    } else {
        __shared__ float sL[EMB * EMB];
        __shared__ float sn[EMB];
        const float* L = g_Lraw + (size_t)kstar * EMB * EMB;
        for (int i = t; i < (EMB * EMB) / 4; i += 64)
            ((float4*)sL)[i] = ((const float4*)L)[i];
        sn[t] = noise[(size_t)b * EMB + t];
        __syncthreads();
        float s = means[kstar * EMB + t];
        for (int j = 0; j <= t; j++) s += sL[t * EMB + j] * sn[j];
        __half h, l; split2h(s, h, l);
        size_t base = (size_t)b * 2 * EMB;
        g_qs[base + t] = h; g_qs[base + EMB + t] = l;
    }

    // ---- idx output ----
    if (t == 0 && out_size >= IDX_OFF + BATCH)
        out[IDX_OFF + b] = (float)kstar;
}

// ---------------- launch ----------------
extern "C" void kernel_launch(void* const* d_in, const int* in_sizes, int n_in,
                              void* d_out, int out_size)
{
    const float* x   = (const float*)d_in[0];
    const float* noi = (const float*)d_in[1];
    const float* eW1 = (const float*)d_in[2];
    const float* eb1 = (const float*)d_in[3];
    const float* eW2 = (const float*)d_in[4];
    const float* eb2 = (const float*)d_in[5];
    const float* eW3 = (const float*)d_in[6];
    const float* eb3 = (const float*)d_in[7];
    const float* dW1 = (const float*)d_in[8];
    const float* db1 = (const float*)d_in[9];
    const float* dW2 = (const float*)d_in[10];
    const float* db2 = (const float*)d_in[11];
    const float* dW3 = (const float*)d_in[12];
    const float* db3 = (const float*)d_in[13];
    const float* means = (const float*)d_in[14];
    const float* sizes = (const float*)d_in[15];
    const float* cov   = (const float*)d_in[16];
    float* out = (float*)d_out;

    __nv_bfloat16 *xs, *h1s, *h2s, *ew1s, *ew2s, *ew3s, *gs, *wp;
    __half *qs, *dw1s, *dw2s, *dw3s;
    float *enc;
    cudaGetSymbolAddress((void**)&xs,  g_xs);
    cudaGetSymbolAddress((void**)&h1s, g_h1s);
    cudaGetSymbolAddress((void**)&h2s, g_h2s);
    cudaGetSymbolAddress((void**)&qs,  g_qs);
    cudaGetSymbolAddress((void**)&ew1s, g_eW1s);
    cudaGetSymbolAddress((void**)&ew2s, g_eW2s);
    cudaGetSymbolAddress((void**)&ew3s, g_eW3s);
    cudaGetSymbolAddress((void**)&dw1s, g_dW1s);
    cudaGetSymbolAddress((void**)&dw2s, g_dW2s);
    cudaGetSymbolAddress((void**)&dw3s, g_dW3s);
    cudaGetSymbolAddress((void**)&gs,  g_Gs);
    cudaGetSymbolAddress((void**)&wp,  g_Wp);
    cudaGetSymbolAddress((void**)&enc, g_enc);

    const int SM128 = 3 * ((128 + 128) * 128);   // 98304
    const int SM64  = 3 * ((64 + 64) * 128);     // 49152
    cudaFuncSetAttribute(mma_gemm<128, 128, 3, 1, 0>, cudaFuncAttributeMaxDynamicSharedMemorySize, SM128);
    cudaFuncSetAttribute(mma_gemm<128, 128, 3, 2, 0>, cudaFuncAttributeMaxDynamicSharedMemorySize, SM128);
    cudaFuncSetAttribute(mma_gemm<64, 64, 3, 0, 0>,   cudaFuncAttributeMaxDynamicSharedMemorySize, SM64);
    cudaFuncSetAttribute(mma_gemm<128, 128, 3, 4, 1>, cudaFuncAttributeMaxDynamicSharedMemorySize, SM128);
    cudaFuncSetAttribute(mma_gemm<128, 128, 3, 0, 1>, cudaFuncAttributeMaxDynamicSharedMemorySize, SM128);

    // 1. all encoder operand converts
    conv_enc_kernel<<<CE_NB, 256>>>(x, eW1, eW2, eW3, xs, ew1s, ew2s, ew3s);
    // 2-4. e1, chol(+flag init), e2
    mma_gemm<128, 128, 3, 1, 0><<<dim3(DENSE / 128, BATCH / 128), 256, SM128>>>(
        xs, ew1s, eb1, h1s, DENSE, 3 * IN_DIM);
    chol_kernel<<<2 * KC, EMB>>>(cov);
    mma_gemm<128, 128, 3, 1, 0><<<dim3(DENSE / 128, BATCH / 128), 256, SM128>>>(
        h1s, ew2s, eb2, h2s, DENSE, 3 * DENSE);
    // 5. identity checks (both matrices)
    ident_check_kernel<<<2 * KC, EMB>>>();
    // 6. e3 -> enc
    mma_gemm<64, 64, 3, 0, 0><<<dim3(EMB / 64, BATCH / 64), 256, SM64>>>(
        h2s, ew3s, eb3, enc, EMB, 3 * DENSE);
    // 7. general-path feature builds (no-op when identity)
    wpg_build_kernel<<<KC + BATCH, 256>>>(means, sizes);
    // 8. general-path lp GEMM (no-op when identity)
    mma_gemm<128, 128, 3, 2, 0><<<dim3(KC / 128, BATCH / 128), 256, SM128>>>(
        gs, wp, nullptr, out + LP_OFF, KC, K3Q);
    // 9. identity-path lp (no-op when general)
    ident_lp_kernel<<<dim3(BATCH / 64, KC / 128), 128>>>(means, sizes, out + LP_OFF);
    // 10. fused argmax/refine/sample/idx
    argmax_sample_kernel<<<BATCH, 64>>>(out + LP_OFF, noi, means, sizes, out, out_size);
    // 11. decoder weight converts
    conv_dec_kernel<<<CD_NB, 256>>>(dW1, dW2, dW3, dw1s, dw2s, dw3s);
    // 12-14. decoder GEMMs
    mma_gemm<128, 128, 3, 4, 1><<<dim3(DENSE / 128, BATCH / 128), 256, SM128>>>(
        qs, dw1s, db1, h1s, DENSE, 2 * EMB);
    mma_gemm<128, 128, 3, 4, 1><<<dim3(DENSE / 128, BATCH / 128), 256, SM128>>>(
        h1s, dw2s, db2, h2s, DENSE, DENSE);
    mma_gemm<128, 128, 3, 0, 1><<<dim3(IN_DIM / 128, BATCH / 128), 256, SM128>>>(
        h2s, dw3s, db3, out, IN_DIM, DENSE);
}